// round 1
// baseline (speedup 1.0000x reference)
#include <cuda_runtime.h>
#include <math.h>

// Problem constants (shapes fixed by the dataset)
#define MAXN 50000
#define MAXE 800000
#define DLAT 128

// ---------------- device scratch (no allocations allowed) ----------------
__device__ float g_dinv[MAXN];
__device__ float g_h[(size_t)MAXN * 128];
__device__ float g_a[(size_t)MAXN * 128];
__device__ float g_b[(size_t)MAXN * 256];   // widest buffer (decoder 256)
__device__ float g_yp[(size_t)MAXN * 10];
__device__ float g_sums[256 * 10];
__device__ float g_cnt[256];

// ---------------- activations ----------------
// ACT: 0 linear+bias, 1 sigmoid, 2 relu, 3 softplus(v-5), 4 linear no-bias
template <int ACT>
__device__ __forceinline__ float apply_act(float v) {
    if (ACT == 1) return 1.f / (1.f + expf(-v));
    if (ACT == 2) return fmaxf(v, 0.f);
    if (ACT == 3) {
        float z = v - 5.f;
        return fmaxf(z, 0.f) + log1pf(expf(-fabsf(z)));
    }
    return v;
}

// ---------------- generic tiled GEMM: C[n,KO] = act(A[n,KI] @ W[KI,KO] + b) ----------------
template <int KI, int KO, int ACT, int ROWS>
__global__ __launch_bounds__(256) void gemm_kernel(
    const float* __restrict__ A, const float* __restrict__ W,
    const float* __restrict__ bias, float* __restrict__ C, int n)
{
    constexpr int BC = (KO < 32) ? KO : 32;   // threads along columns
    constexpr int BR = 256 / BC;              // thread groups along rows
    constexpr int RT = ROWS / BR;             // rows per thread
    constexpr int CT = KO / BC;               // cols per thread
    constexpr int KC = (KI < 32) ? KI : 32;   // K chunk

    __shared__ float As[ROWS][KC];
    __shared__ float Ws[KC][KO];

    const int tid = threadIdx.x;
    const int tx = tid % BC;
    const int ty = tid / BC;
    const int row0 = blockIdx.x * ROWS;

    float acc[RT][CT];
#pragma unroll
    for (int i = 0; i < RT; i++)
#pragma unroll
        for (int j = 0; j < CT; j++) acc[i][j] = 0.f;

    for (int k0 = 0; k0 < KI; k0 += KC) {
        if (k0) __syncthreads();
        // load W chunk (contiguous)
        for (int i = tid; i < KC * KO; i += 256)
            Ws[i / KO][i % KO] = W[(size_t)k0 * KO + i];
        // load A tile chunk (coalesced 32-wide per row segment)
        for (int i = tid; i < ROWS * KC; i += 256) {
            int r = i / KC, kk = i % KC;
            int gr = row0 + r;
            As[r][kk] = (gr < n) ? A[(size_t)gr * KI + k0 + kk] : 0.f;
        }
        __syncthreads();
#pragma unroll
        for (int kk = 0; kk < KC; kk++) {
            float av[RT], wv[CT];
#pragma unroll
            for (int i = 0; i < RT; i++) av[i] = As[ty * RT + i][kk];
#pragma unroll
            for (int j = 0; j < CT; j++) wv[j] = Ws[kk][j * BC + tx];
#pragma unroll
            for (int i = 0; i < RT; i++)
#pragma unroll
                for (int j = 0; j < CT; j++) acc[i][j] += av[i] * wv[j];
        }
    }

#pragma unroll
    for (int j = 0; j < CT; j++) {
        int col = j * BC + tx;
        float bv = (ACT == 4) ? 0.f : bias[col];
#pragma unroll
        for (int i = 0; i < RT; i++) {
            int r = row0 + ty * RT + i;
            if (r < n) C[(size_t)r * KO + col] = apply_act<ACT>(acc[i][j] + bv);
        }
    }
}

// ---------------- degree / dinv ----------------
__global__ void k_deg_init(float* dinv, int n) {
    int i = blockIdx.x * blockDim.x + threadIdx.x;
    if (i < n) dinv[i] = 1.f;   // self-loop
}
__global__ void k_deg_acc(const int* __restrict__ dst, float* dinv, int E) {
    int i = blockIdx.x * blockDim.x + threadIdx.x;
    if (i < E) atomicAdd(&dinv[dst[i]], 1.f);
}
__global__ void k_deg_fin(float* dinv, int n) {
    int i = blockIdx.x * blockDim.x + threadIdx.x;
    if (i < n) dinv[i] = rsqrtf(dinv[i]);
}

// ---------------- GCN scatter ----------------
// init: o = g * dinv[n]^2 + b_gcn   (float4 over n*32 groups)
__global__ void k_scatter_init(const float* __restrict__ g, const float* __restrict__ dinv,
                               const float* __restrict__ bias, float* __restrict__ o, int n)
{
    int i = blockIdx.x * blockDim.x + threadIdx.x;
    if (i >= n * 32) return;
    int node = i >> 5;
    int c4 = (i & 31) * 4;
    float dv = dinv[node];
    float s = dv * dv;
    float4 v = *(const float4*)(g + (size_t)node * 128 + c4);
    float4 r;
    r.x = v.x * s + bias[c4 + 0];
    r.y = v.y * s + bias[c4 + 1];
    r.z = v.z * s + bias[c4 + 2];
    r.w = v.w * s + bias[c4 + 3];
    *(float4*)(o + (size_t)node * 128 + c4) = r;
}

// edges: warp per edge, lane handles 4 floats, vector reduction atomics
__global__ void k_scatter_edges(const int* __restrict__ src, const int* __restrict__ dst,
                                const float* __restrict__ dinv, const float* __restrict__ g,
                                float* __restrict__ o, int E)
{
    int t = blockIdx.x * blockDim.x + threadIdx.x;
    int e = t >> 5;
    if (e >= E) return;   // warp-uniform
    int lane = t & 31;
    int s = 0, d = 0;
    float w = 0.f;
    if (lane == 0) {
        s = src[e];
        d = dst[e];
        w = dinv[s] * dinv[d];
    }
    s = __shfl_sync(0xffffffffu, s, 0);
    d = __shfl_sync(0xffffffffu, d, 0);
    w = __shfl_sync(0xffffffffu, w, 0);
    float4 v = *(const float4*)(g + (size_t)s * 128 + lane * 4);
    float* p = o + (size_t)d * 128 + lane * 4;
    asm volatile("red.global.add.v4.f32 [%0], {%1, %2, %3, %4};"
                 :: "l"(p), "f"(v.x * w), "f"(v.y * w), "f"(v.z * w), "f"(v.w * w)
                 : "memory");
}

// ---------------- reparametrization: h = mu + std * eps ----------------
__global__ void k_hupdate(const float* __restrict__ mu, const float* __restrict__ sd,
                          const float* __restrict__ eps, float* __restrict__ h, int cnt4)
{
    int i = blockIdx.x * blockDim.x + threadIdx.x;
    if (i >= cnt4) return;
    float4 m = ((const float4*)mu)[i];
    float4 s = ((const float4*)sd)[i];
    float4 e = ((const float4*)eps)[i];
    float4 r;
    r.x = m.x + s.x * e.x;
    r.y = m.y + s.y * e.y;
    r.z = m.z + s.z * e.z;
    r.w = m.w + s.w * e.w;
    ((float4*)h)[i] = r;
}

// ---------------- final 16 -> 10 layer, sigmoid ----------------
__global__ void k_final10(const float* __restrict__ A, const float* __restrict__ Wo,
                          const float* __restrict__ bo, float* __restrict__ yp, int n)
{
    __shared__ float w[160];
    __shared__ float bb[10];
    if (threadIdx.x < 160) w[threadIdx.x] = Wo[threadIdx.x];
    if (threadIdx.x < 10) bb[threadIdx.x] = bo[threadIdx.x];
    __syncthreads();
    int i = blockIdx.x * blockDim.x + threadIdx.x;
    if (i >= n) return;
    float a[16];
#pragma unroll
    for (int k = 0; k < 16; k++) a[k] = A[(size_t)i * 16 + k];
#pragma unroll
    for (int c = 0; c < 10; c++) {
        float s = bb[c];
#pragma unroll
        for (int k = 0; k < 16; k++) s += a[k] * w[k * 10 + c];
        yp[(size_t)i * 10 + c] = 1.f / (1.f + expf(-s));
    }
}

// ---------------- pooling ----------------
__global__ void k_pool_init(float* sums, float* cnt, int gsz) {
    int i = blockIdx.x * blockDim.x + threadIdx.x;
    if (i < gsz * 10) sums[i] = 0.f;
    if (i < gsz) cnt[i] = 0.f;
}
__global__ void k_pool_acc(const float* __restrict__ yp, const int* __restrict__ bids,
                           float* sums, float* cnt, int n)
{
    int i = blockIdx.x * blockDim.x + threadIdx.x;
    if (i >= n) return;
    int b = bids[i];
    const float* r = yp + (size_t)i * 10;
#pragma unroll
    for (int c = 0; c < 10; c++) atomicAdd(&sums[b * 10 + c], r[c]);
    atomicAdd(&cnt[b], 1.f);
}
__global__ void k_pool_fin(const float* __restrict__ sums, const float* __restrict__ cnt,
                           const float* __restrict__ y, float* __restrict__ out,
                           float* __restrict__ yout, int tot)
{
    int i = blockIdx.x * blockDim.x + threadIdx.x;
    if (i >= tot) return;
    out[i] = sums[i] / fmaxf(cnt[i / 10], 1.f);
    yout[i] = y[i];
}

// ---------------- host launch ----------------
extern "C" void kernel_launch(void* const* d_in, const int* in_sizes, int n_in,
                              void* d_out, int out_size)
{
    const float* x     = (const float*)d_in[0];
    const int*   ei    = (const int*)d_in[1];
    const int*   bids  = (const int*)d_in[2];
    const float* y     = (const float*)d_in[3];
    const float* eps   = (const float*)d_in[4];
    const float* W_in  = (const float*)d_in[5];
    const float* b_in  = (const float*)d_in[6];
    const float* W_gcn = (const float*)d_in[7];
    const float* b_gcn = (const float*)d_in[8];
    const float* W_enc = (const float*)d_in[9];
    const float* b_enc = (const float*)d_in[10];
    const float* W_mu  = (const float*)d_in[11];
    const float* b_mu  = (const float*)d_in[12];
    const float* W_std = (const float*)d_in[13];
    const float* b_std = (const float*)d_in[14];
    const float* Wd0 = (const float*)d_in[15]; const float* bd0 = (const float*)d_in[16];
    const float* Wd1 = (const float*)d_in[17]; const float* bd1 = (const float*)d_in[18];
    const float* Wd2 = (const float*)d_in[19]; const float* bd2 = (const float*)d_in[20];
    const float* Wd3 = (const float*)d_in[21]; const float* bd3 = (const float*)d_in[22];
    const float* Wd4 = (const float*)d_in[23]; const float* bd4 = (const float*)d_in[24];
    const float* Wo  = (const float*)d_in[25]; const float* bo  = (const float*)d_in[26];

    const int N = in_sizes[2];        // batch_ids count
    const int E = in_sizes[1] / 2;    // edge_index [2,E]
    const int G = in_sizes[3] / 10;   // y [G,10]
    const int* src = ei;
    const int* dst = ei + E;

    float *dinv, *h, *a, *b, *yp, *sums, *cnt;
    cudaGetSymbolAddress((void**)&dinv, g_dinv);
    cudaGetSymbolAddress((void**)&h,    g_h);
    cudaGetSymbolAddress((void**)&a,    g_a);
    cudaGetSymbolAddress((void**)&b,    g_b);
    cudaGetSymbolAddress((void**)&yp,   g_yp);
    cudaGetSymbolAddress((void**)&sums, g_sums);
    cudaGetSymbolAddress((void**)&cnt,  g_cnt);

    float* out    = (float*)d_out;
    float* mu_out = out + (size_t)G * 10;
    float* sd_out = mu_out + (size_t)N * 128;
    float* y_out  = sd_out + (size_t)N * 128;

    const int TB = 256;
    const int gb128 = (N + 127) / 128;
    const int gb64  = (N + 63) / 64;

    // degrees + dinv
    k_deg_init<<<(N + TB - 1) / TB, TB>>>(dinv, N);
    k_deg_acc<<<(E + TB - 1) / TB, TB>>>(dst, dinv, E);
    k_deg_fin<<<(N + TB - 1) / TB, TB>>>(dinv, N);

    // input layer: h = sigmoid(x @ W_in + b_in)
    gemm_kernel<32, 128, 1, 128><<<gb128, TB>>>(x, W_in, b_in, h, N);

    // K = 3 hops
    for (int hop = 0; hop < 3; hop++) {
        gemm_kernel<128, 128, 4, 128><<<gb128, TB>>>(h, W_gcn, nullptr, a, N);
        k_scatter_init<<<((size_t)N * 32 + TB - 1) / TB, TB>>>(a, dinv, b_gcn, b, N);
        k_scatter_edges<<<((size_t)E * 32 + TB - 1) / TB, TB>>>(src, dst, dinv, a, b, E);
        // 5 encoder layers (sigmoid), ping-pong b <-> a, ends in a
        gemm_kernel<128, 128, 1, 128><<<gb128, TB>>>(b, W_enc + 0 * 16384, b_enc + 0 * 128, a, N);
        gemm_kernel<128, 128, 1, 128><<<gb128, TB>>>(a, W_enc + 1 * 16384, b_enc + 1 * 128, b, N);
        gemm_kernel<128, 128, 1, 128><<<gb128, TB>>>(b, W_enc + 2 * 16384, b_enc + 2 * 128, a, N);
        gemm_kernel<128, 128, 1, 128><<<gb128, TB>>>(a, W_enc + 3 * 16384, b_enc + 3 * 128, b, N);
        gemm_kernel<128, 128, 1, 128><<<gb128, TB>>>(b, W_enc + 4 * 16384, b_enc + 4 * 128, a, N);
        // mu / std straight into output regions (only last hop survives, like ref)
        gemm_kernel<128, 128, 0, 128><<<gb128, TB>>>(a, W_mu, b_mu, mu_out, N);
        gemm_kernel<128, 128, 3, 128><<<gb128, TB>>>(a, W_std, b_std, sd_out, N);
        k_hupdate<<<((size_t)N * 32 + TB - 1) / TB, TB>>>(mu_out, sd_out,
                                                          eps + (size_t)hop * N * 128, h, N * 32);
    }

    // decoder MLP: 128 -> 256 -> 128 -> 64 -> 32 -> 16 -> 10
    gemm_kernel<128, 256, 2, 64><<<gb64,  TB>>>(h, Wd0, bd0, b, N);
    gemm_kernel<256, 128, 2, 128><<<gb128, TB>>>(b, Wd1, bd1, a, N);
    gemm_kernel<128, 64,  2, 128><<<gb128, TB>>>(a, Wd2, bd2, b, N);
    gemm_kernel<64,  32,  2, 128><<<gb128, TB>>>(b, Wd3, bd3, a, N);
    gemm_kernel<32,  16,  2, 128><<<gb128, TB>>>(a, Wd4, bd4, b, N);
    k_final10<<<(N + TB - 1) / TB, TB>>>(b, Wo, bo, yp, N);

    // global mean pool + y passthrough
    k_pool_init<<<(G * 10 + TB - 1) / TB, TB>>>(sums, cnt, G);
    k_pool_acc<<<(N + TB - 1) / TB, TB>>>(yp, bids, sums, cnt, N);
    k_pool_fin<<<(G * 10 + TB - 1) / TB, TB>>>(sums, cnt, y, out, y_out, G * 10);
}

// round 3
// speedup vs baseline: 1.0987x; 1.0987x over previous
#include <cuda_runtime.h>
#include <cuda_bf16.h>
#include <mma.h>
#include <math.h>
#include <stdint.h>

using namespace nvcuda;

#define MAXN 50000

// ---------------- device scratch ----------------
__device__ float g_dinv[MAXN];
__device__ float g_h[(size_t)MAXN * 128];
__device__ float g_a[(size_t)MAXN * 128];
__device__ float g_b[(size_t)MAXN * 256];
__device__ float g_yp[(size_t)MAXN * 10];
__device__ float g_sums[256 * 10];
__device__ float g_cnt[256];

// ---------------- activations ----------------
// ACT: 0 linear+bias, 1 sigmoid, 2 relu, 3 softplus(v-5), 4 linear no-bias
template <int ACT>
__device__ __forceinline__ float apply_act(float v) {
    if (ACT == 1) return 1.f / (1.f + expf(-v));
    if (ACT == 2) return fmaxf(v, 0.f);
    if (ACT == 3) {
        float z = v - 5.f;
        return fmaxf(z, 0.f) + log1pf(expf(-fabsf(z)));
    }
    return v;
}

__device__ __forceinline__ uint32_t pack2bf(float a, float b) {
    __nv_bfloat16 ha = __float2bfloat16(a), hb = __float2bfloat16(b);
    return (uint32_t)__bfloat16_as_ushort(ha) | ((uint32_t)__bfloat16_as_ushort(hb) << 16);
}
__device__ __forceinline__ uint32_t pack2bf_lo(float a, float b) {
    __nv_bfloat16 ha = __float2bfloat16(a), hb = __float2bfloat16(b);
    float ra = a - __bfloat162float(ha), rb = b - __bfloat162float(hb);
    __nv_bfloat16 la = __float2bfloat16(ra), lb = __float2bfloat16(rb);
    return (uint32_t)__bfloat16_as_ushort(la) | ((uint32_t)__bfloat16_as_ushort(lb) << 16);
}

// ---------------- WMMA GEMM: C[n, :KO] = act(A[n,KI] @ W[:, col-slice] + b) ----------------
// A: fp32 [n, KI] row-major (row stride = KI)
// W: fp32, row stride ldw, pre-offset to the desired column slice; KO columns used
// C: fp32, row stride ldc, pre-offset to the output column slice
// 3-term bf16 split for fp32-like precision on tensor pipe.
template <int KI, int KO, int ACT>
__global__ __launch_bounds__(256) void wm_gemm(
    const float* __restrict__ A, const float* __restrict__ W, int ldw,
    const float* __restrict__ bias, float* __restrict__ C, int ldc, int n)
{
    constexpr int KC  = (KI < 128) ? KI : 128;   // K chunk
    constexpr int NCH = KI / KC;
    constexpr int LDA = KC + 8;                  // bf16 elems per A smem row
    constexpr int LDW = KO + 8;                  // bf16 elems per W smem row
    constexpr int NJT = KO / 16;                 // col tiles per warp
    constexpr int AE  = 128 * LDA;               // elems per A split buffer
    constexpr int WE  = KC * LDW;

    extern __shared__ char smraw[];
    __nv_bfloat16* sAhi = (__nv_bfloat16*)smraw;
    __nv_bfloat16* sAlo = sAhi + AE;
    __nv_bfloat16* sWhi = sAlo + AE;
    __nv_bfloat16* sWlo = sWhi + WE;
    float* stage = (float*)(sWlo + WE);          // 8 warps x 16 x 20 fp32

    const int tid  = threadIdx.x;
    const int wid  = tid >> 5;
    const int lane = tid & 31;
    const int row0 = blockIdx.x * 128;

    wmma::fragment<wmma::accumulator, 16, 16, 16, float> acc[NJT];
#pragma unroll
    for (int j = 0; j < NJT; j++) wmma::fill_fragment(acc[j], 0.f);

    for (int ch = 0; ch < NCH; ch++) {
        if (ch) __syncthreads();
        // ---- load & split A chunk ----
        {
            constexpr int Q = KC / 4;
            for (int i = tid; i < 128 * Q; i += 256) {
                int r = i / Q, q = i % Q;
                float4 v = make_float4(0.f, 0.f, 0.f, 0.f);
                if (row0 + r < n)
                    v = *(const float4*)(A + (size_t)(row0 + r) * KI + ch * KC + 4 * q);
                uint2 hv, lv;
                hv.x = pack2bf(v.x, v.y);    hv.y = pack2bf(v.z, v.w);
                lv.x = pack2bf_lo(v.x, v.y); lv.y = pack2bf_lo(v.z, v.w);
                *(uint2*)(sAhi + r * LDA + 4 * q) = hv;
                *(uint2*)(sAlo + r * LDA + 4 * q) = lv;
            }
        }
        // ---- load & split W chunk ----
        {
            constexpr int Q = KO / 4;
            for (int i = tid; i < KC * Q; i += 256) {
                int k = i / Q, q = i % Q;
                float4 v = *(const float4*)(W + (size_t)(ch * KC + k) * ldw + 4 * q);
                uint2 hv, lv;
                hv.x = pack2bf(v.x, v.y);    hv.y = pack2bf(v.z, v.w);
                lv.x = pack2bf_lo(v.x, v.y); lv.y = pack2bf_lo(v.z, v.w);
                *(uint2*)(sWhi + k * LDW + 4 * q) = hv;
                *(uint2*)(sWlo + k * LDW + 4 * q) = lv;
            }
        }
        __syncthreads();

        // ---- MMA ----
#pragma unroll
        for (int k = 0; k < KC / 16; k++) {
            wmma::fragment<wmma::matrix_a, 16, 16, 16, __nv_bfloat16, wmma::row_major> ahi, alo;
            wmma::load_matrix_sync(ahi, sAhi + (wid * 16) * LDA + k * 16, LDA);
            wmma::load_matrix_sync(alo, sAlo + (wid * 16) * LDA + k * 16, LDA);
#pragma unroll
            for (int j = 0; j < NJT; j++) {
                wmma::fragment<wmma::matrix_b, 16, 16, 16, __nv_bfloat16, wmma::row_major> bhi, blo;
                wmma::load_matrix_sync(bhi, sWhi + (k * 16) * LDW + j * 16, LDW);
                wmma::load_matrix_sync(blo, sWlo + (k * 16) * LDW + j * 16, LDW);
                wmma::mma_sync(acc[j], ahi, bhi, acc[j]);
                wmma::mma_sync(acc[j], ahi, blo, acc[j]);
                wmma::mma_sync(acc[j], alo, bhi, acc[j]);
            }
        }
    }

    // ---- epilogue: per-warp stage, bias + act, vectorized store ----
    float* st = stage + wid * 16 * 20;
    const int r8 = lane >> 1;          // 0..15
    const int c8 = (lane & 1) * 8;     // 0 or 8
    const int grow = row0 + wid * 16 + r8;
#pragma unroll
    for (int j = 0; j < NJT; j++) {
        wmma::store_matrix_sync(st, acc[j], 20, wmma::mem_row_major);
        __syncwarp();
        if (grow < n) {
            float o[8];
#pragma unroll
            for (int q = 0; q < 8; q++) {
                float v = st[r8 * 20 + c8 + q];
                if (ACT != 4) v += bias[j * 16 + c8 + q];
                o[q] = apply_act<ACT>(v);
            }
            float* p = C + (size_t)grow * ldc + j * 16 + c8;
            *(float4*)(p + 0) = make_float4(o[0], o[1], o[2], o[3]);
            *(float4*)(p + 4) = make_float4(o[4], o[5], o[6], o[7]);
        }
        __syncwarp();
    }
}

// ---------------- SIMT GEMM (tiny decoder layers) ----------------
template <int KI, int KO, int ACT, int ROWS>
__global__ __launch_bounds__(256) void gemm_kernel(
    const float* __restrict__ A, const float* __restrict__ W,
    const float* __restrict__ bias, float* __restrict__ C, int n)
{
    constexpr int BC = (KO < 32) ? KO : 32;
    constexpr int BR = 256 / BC;
    constexpr int RT = ROWS / BR;
    constexpr int CT = KO / BC;
    constexpr int KC = (KI < 32) ? KI : 32;

    __shared__ float As[ROWS][KC];
    __shared__ float Ws[KC][KO];
    const int tid = threadIdx.x;
    const int tx = tid % BC;
    const int ty = tid / BC;
    const int row0 = blockIdx.x * ROWS;

    float acc[RT][CT];
#pragma unroll
    for (int i = 0; i < RT; i++)
#pragma unroll
        for (int j = 0; j < CT; j++) acc[i][j] = 0.f;

    for (int k0 = 0; k0 < KI; k0 += KC) {
        if (k0) __syncthreads();
        for (int i = tid; i < KC * KO; i += 256)
            Ws[i / KO][i % KO] = W[(size_t)k0 * KO + i];
        for (int i = tid; i < ROWS * KC; i += 256) {
            int r = i / KC, kk = i % KC;
            int gr = row0 + r;
            As[r][kk] = (gr < n) ? A[(size_t)gr * KI + k0 + kk] : 0.f;
        }
        __syncthreads();
#pragma unroll
        for (int kk = 0; kk < KC; kk++) {
            float av[RT], wv[CT];
#pragma unroll
            for (int i = 0; i < RT; i++) av[i] = As[ty * RT + i][kk];
#pragma unroll
            for (int j = 0; j < CT; j++) wv[j] = Ws[kk][j * BC + tx];
#pragma unroll
            for (int i = 0; i < RT; i++)
#pragma unroll
                for (int j = 0; j < CT; j++) acc[i][j] += av[i] * wv[j];
        }
    }
#pragma unroll
    for (int j = 0; j < CT; j++) {
        int col = j * BC + tx;
        float bv = bias[col];
#pragma unroll
        for (int i = 0; i < RT; i++) {
            int r = row0 + ty * RT + i;
            if (r < n) C[(size_t)r * KO + col] = apply_act<ACT>(acc[i][j] + bv);
        }
    }
}

// ---------------- degree / dinv ----------------
__global__ void k_deg_init(float* dinv, int n) {
    int i = blockIdx.x * blockDim.x + threadIdx.x;
    if (i < n) dinv[i] = 1.f;
}
__global__ void k_deg_acc(const int* __restrict__ dst, float* dinv, int E) {
    int i = blockIdx.x * blockDim.x + threadIdx.x;
    if (i < E) atomicAdd(&dinv[dst[i]], 1.f);
}
__global__ void k_deg_fin(float* dinv, int n) {
    int i = blockIdx.x * blockDim.x + threadIdx.x;
    if (i < n) dinv[i] = rsqrtf(dinv[i]);
}

// ---------------- GCN scatter ----------------
__global__ void k_scatter_init(const float* __restrict__ g, const float* __restrict__ dinv,
                               const float* __restrict__ bias, float* __restrict__ o, int n)
{
    int i = blockIdx.x * blockDim.x + threadIdx.x;
    if (i >= n * 32) return;
    int node = i >> 5;
    int c4 = (i & 31) * 4;
    float dv = dinv[node];
    float s = dv * dv;
    float4 v = *(const float4*)(g + (size_t)node * 128 + c4);
    float4 r;
    r.x = v.x * s + bias[c4 + 0];
    r.y = v.y * s + bias[c4 + 1];
    r.z = v.z * s + bias[c4 + 2];
    r.w = v.w * s + bias[c4 + 3];
    *(float4*)(o + (size_t)node * 128 + c4) = r;
}

__global__ void k_scatter_edges(const int* __restrict__ src, const int* __restrict__ dst,
                                const float* __restrict__ dinv, const float* __restrict__ g,
                                float* __restrict__ o, int E)
{
    int t = blockIdx.x * blockDim.x + threadIdx.x;
    int e = t >> 5;
    if (e >= E) return;
    int lane = t & 31;
    int s = 0, d = 0;
    float w = 0.f;
    if (lane == 0) {
        s = src[e];
        d = dst[e];
        w = dinv[s] * dinv[d];
    }
    s = __shfl_sync(0xffffffffu, s, 0);
    d = __shfl_sync(0xffffffffu, d, 0);
    w = __shfl_sync(0xffffffffu, w, 0);
    float4 v = *(const float4*)(g + (size_t)s * 128 + lane * 4);
    float* p = o + (size_t)d * 128 + lane * 4;
    asm volatile("red.global.add.v4.f32 [%0], {%1, %2, %3, %4};"
                 :: "l"(p), "f"(v.x * w), "f"(v.y * w), "f"(v.z * w), "f"(v.w * w)
                 : "memory");
}

// ---------------- reparametrization ----------------
__global__ void k_hupdate(const float* __restrict__ mu, const float* __restrict__ sd,
                          const float* __restrict__ eps, float* __restrict__ h, int cnt4)
{
    int i = blockIdx.x * blockDim.x + threadIdx.x;
    if (i >= cnt4) return;
    float4 m = ((const float4*)mu)[i];
    float4 s = ((const float4*)sd)[i];
    float4 e = ((const float4*)eps)[i];
    float4 r;
    r.x = m.x + s.x * e.x;
    r.y = m.y + s.y * e.y;
    r.z = m.z + s.z * e.z;
    r.w = m.w + s.w * e.w;
    ((float4*)h)[i] = r;
}

// ---------------- final 16 -> 10 ----------------
__global__ void k_final10(const float* __restrict__ A, const float* __restrict__ Wo,
                          const float* __restrict__ bo, float* __restrict__ yp, int n)
{
    __shared__ float w[160];
    __shared__ float bb[10];
    if (threadIdx.x < 160) w[threadIdx.x] = Wo[threadIdx.x];
    if (threadIdx.x < 10) bb[threadIdx.x] = bo[threadIdx.x];
    __syncthreads();
    int i = blockIdx.x * blockDim.x + threadIdx.x;
    if (i >= n) return;
    float a[16];
#pragma unroll
    for (int k = 0; k < 16; k++) a[k] = A[(size_t)i * 16 + k];
#pragma unroll
    for (int c = 0; c < 10; c++) {
        float s = bb[c];
#pragma unroll
        for (int k = 0; k < 16; k++) s += a[k] * w[k * 10 + c];
        yp[(size_t)i * 10 + c] = 1.f / (1.f + expf(-s));
    }
}

// ---------------- pooling ----------------
__global__ void k_pool_init(float* sums, float* cnt, int gsz) {
    int i = blockIdx.x * blockDim.x + threadIdx.x;
    if (i < gsz * 10) sums[i] = 0.f;
    if (i < gsz) cnt[i] = 0.f;
}
__global__ void k_pool_acc(const float* __restrict__ yp, const int* __restrict__ bids,
                           float* sums, float* cnt, int n)
{
    int i = blockIdx.x * blockDim.x + threadIdx.x;
    if (i >= n) return;
    int b = bids[i];
    const float* r = yp + (size_t)i * 10;
#pragma unroll
    for (int c = 0; c < 10; c++) atomicAdd(&sums[b * 10 + c], r[c]);
    atomicAdd(&cnt[b], 1.f);
}
__global__ void k_pool_fin(const float* __restrict__ sums, const float* __restrict__ cnt,
                           const float* __restrict__ y, float* __restrict__ out,
                           float* __restrict__ yout, int tot)
{
    int i = blockIdx.x * blockDim.x + threadIdx.x;
    if (i >= tot) return;
    out[i] = sums[i] / fmaxf(cnt[i / 10], 1.f);
    yout[i] = y[i];
}

// ---------------- host ----------------
template <int KI, int KO, int ACT>
static void run_wm(const float* A, const float* W, int ldw, const float* bias,
                   float* C, int ldc, int n)
{
    constexpr int KC = (KI < 128) ? KI : 128;
    constexpr int AE = 128 * (KC + 8);
    constexpr int WE = KC * (KO + 8);
    constexpr int SMB = (2 * AE + 2 * WE) * 2 + 8 * 16 * 20 * 4;
    cudaFuncSetAttribute(wm_gemm<KI, KO, ACT>, cudaFuncAttributeMaxDynamicSharedMemorySize, SMB);
    wm_gemm<KI, KO, ACT><<<(n + 127) / 128, 256, SMB>>>(A, W, ldw, bias, C, ldc, n);
}

extern "C" void kernel_launch(void* const* d_in, const int* in_sizes, int n_in,
                              void* d_out, int out_size)
{
    const float* x     = (const float*)d_in[0];
    const int*   ei    = (const int*)d_in[1];
    const int*   bids  = (const int*)d_in[2];
    const float* y     = (const float*)d_in[3];
    const float* eps   = (const float*)d_in[4];
    const float* W_in  = (const float*)d_in[5];
    const float* b_in  = (const float*)d_in[6];
    const float* W_gcn = (const float*)d_in[7];
    const float* b_gcn = (const float*)d_in[8];
    const float* W_enc = (const float*)d_in[9];
    const float* b_enc = (const float*)d_in[10];
    const float* W_mu  = (const float*)d_in[11];
    const float* b_mu  = (const float*)d_in[12];
    const float* W_std = (const float*)d_in[13];
    const float* b_std = (const float*)d_in[14];
    const float* Wd0 = (const float*)d_in[15]; const float* bd0 = (const float*)d_in[16];
    const float* Wd1 = (const float*)d_in[17]; const float* bd1 = (const float*)d_in[18];
    const float* Wd2 = (const float*)d_in[19]; const float* bd2 = (const float*)d_in[20];
    const float* Wd3 = (const float*)d_in[21]; const float* bd3 = (const float*)d_in[22];
    const float* Wd4 = (const float*)d_in[23]; const float* bd4 = (const float*)d_in[24];
    const float* Wo  = (const float*)d_in[25]; const float* bo  = (const float*)d_in[26];

    const int N = in_sizes[2];
    const int E = in_sizes[1] / 2;
    const int G = in_sizes[3] / 10;
    const int* src = ei;
    const int* dst = ei + E;

    float *dinv, *h, *a, *b, *yp, *sums, *cnt;
    cudaGetSymbolAddress((void**)&dinv, g_dinv);
    cudaGetSymbolAddress((void**)&h,    g_h);
    cudaGetSymbolAddress((void**)&a,    g_a);
    cudaGetSymbolAddress((void**)&b,    g_b);
    cudaGetSymbolAddress((void**)&yp,   g_yp);
    cudaGetSymbolAddress((void**)&sums, g_sums);
    cudaGetSymbolAddress((void**)&cnt,  g_cnt);

    float* out    = (float*)d_out;
    float* mu_out = out + (size_t)G * 10;
    float* sd_out = mu_out + (size_t)N * 128;
    float* y_out  = sd_out + (size_t)N * 128;

    const int TB = 256;
    const int gb128 = (N + 127) / 128;

    // degrees
    k_deg_init<<<(N + TB - 1) / TB, TB>>>(dinv, N);
    k_deg_acc<<<(E + TB - 1) / TB, TB>>>(dst, dinv, E);
    k_deg_fin<<<(N + TB - 1) / TB, TB>>>(dinv, N);

    // input layer: h = sigmoid(x @ W_in + b_in)
    run_wm<32, 128, 1>(x, W_in, 128, b_in, h, 128, N);

    for (int hop = 0; hop < 3; hop++) {
        run_wm<128, 128, 4>(h, W_gcn, 128, nullptr, a, 128, N);
        k_scatter_init<<<((size_t)N * 32 + TB - 1) / TB, TB>>>(a, dinv, b_gcn, b, N);
        k_scatter_edges<<<((size_t)E * 32 + TB - 1) / TB, TB>>>(src, dst, dinv, a, b, E);
        run_wm<128, 128, 1>(b, W_enc + 0 * 16384, 128, b_enc + 0 * 128, a, 128, N);
        run_wm<128, 128, 1>(a, W_enc + 1 * 16384, 128, b_enc + 1 * 128, b, 128, N);
        run_wm<128, 128, 1>(b, W_enc + 2 * 16384, 128, b_enc + 2 * 128, a, 128, N);
        run_wm<128, 128, 1>(a, W_enc + 3 * 16384, 128, b_enc + 3 * 128, b, 128, N);
        run_wm<128, 128, 1>(b, W_enc + 4 * 16384, 128, b_enc + 4 * 128, a, 128, N);
        run_wm<128, 128, 0>(a, W_mu,  128, b_mu,  mu_out, 128, N);
        run_wm<128, 128, 3>(a, W_std, 128, b_std, sd_out, 128, N);
        k_hupdate<<<((size_t)N * 32 + TB - 1) / TB, TB>>>(mu_out, sd_out,
                                                          eps + (size_t)hop * N * 128, h, N * 32);
    }

    // decoder: 128 -> 256 (two column halves) -> 128 -> 64 -> 32 -> 16 -> 10
    run_wm<128, 128, 2>(h, Wd0,       256, bd0,       b,       256, N);
    run_wm<128, 128, 2>(h, Wd0 + 128, 256, bd0 + 128, b + 128, 256, N);
    run_wm<256, 128, 2>(b, Wd1, 128, bd1, a, 128, N);
    run_wm<128, 64,  2>(a, Wd2, 64,  bd2, b, 64,  N);
    gemm_kernel<64, 32, 2, 128><<<gb128, TB>>>(b, Wd3, bd3, a, N);
    gemm_kernel<32, 16, 2, 128><<<gb128, TB>>>(a, Wd4, bd4, b, N);
    k_final10<<<(N + TB - 1) / TB, TB>>>(b, Wo, bo, yp, N);

    // pooling
    k_pool_init<<<(G * 10 + TB - 1) / TB, TB>>>(sums, cnt, G);
    k_pool_acc<<<(N + TB - 1) / TB, TB>>>(yp, bids, sums, cnt, N);
    k_pool_fin<<<(G * 10 + TB - 1) / TB, TB>>>(sums, cnt, y, out, y_out, G * 10);
}

// round 4
// speedup vs baseline: 1.7095x; 1.5559x over previous
#include <cuda_runtime.h>
#include <cuda_bf16.h>
#include <mma.h>
#include <math.h>
#include <stdint.h>

using namespace nvcuda;

#define MAXN  50000
#define NPAD  50176   // rows padded to multiple of 128 for safe cp.async

// ---------------- device scratch ----------------
__device__ float g_dinv[MAXN];
__device__ float g_a[(size_t)MAXN * 128];
__device__ float g_b[(size_t)MAXN * 256];
__device__ float g_yp[(size_t)MAXN * 10];
__device__ float g_sums[256 * 10];
__device__ float g_cnt[256];

// bf16 hi/lo activation planes (zero-padded rows beyond n stay zero)
__device__ __nv_bfloat16 g_hhi[(size_t)NPAD * 128];
__device__ __nv_bfloat16 g_hlo[(size_t)NPAD * 128];
__device__ __nv_bfloat16 g_p0hi[(size_t)NPAD * 256];
__device__ __nv_bfloat16 g_p0lo[(size_t)NPAD * 256];
__device__ __nv_bfloat16 g_p1hi[(size_t)NPAD * 256];
__device__ __nv_bfloat16 g_p1lo[(size_t)NPAD * 256];

// bf16 hi/lo weight planes, layout identical to fp32 source [KI,KO]
#define WOFF_IN  0
#define WOFF_GCN 4096
#define WOFF_ENC 20480
#define WOFF_MU  102400
#define WOFF_STD 118784
#define WOFF_D0  135168
#define WOFF_D1  167936
#define WOFF_D2  200704
#define WTOT     208896
__device__ __nv_bfloat16 g_whi[WTOT];
__device__ __nv_bfloat16 g_wlo[WTOT];

// ---------------- helpers ----------------
__device__ __forceinline__ uint32_t smem_u32(const void* p) {
    uint32_t a;
    asm("{ .reg .u64 t; cvta.to.shared.u64 t, %1; cvt.u32.u64 %0, t; }" : "=r"(a) : "l"(p));
    return a;
}
__device__ __forceinline__ void cpa16(uint32_t dst, const void* src) {
    asm volatile("cp.async.ca.shared.global [%0], [%1], 16;" :: "r"(dst), "l"(src));
}
#define CPA_COMMIT() asm volatile("cp.async.commit_group;" ::: "memory")
#define CPA_WAIT()   asm volatile("cp.async.wait_group 0;" ::: "memory")

// ACT: 0 linear+bias, 1 sigmoid, 2 relu, 3 softplus(v-5), 4 linear no-bias
template <int ACT>
__device__ __forceinline__ float apply_act(float v) {
    if (ACT == 1) return 1.f / (1.f + expf(-v));
    if (ACT == 2) return fmaxf(v, 0.f);
    if (ACT == 3) {
        float z = v - 5.f;
        return fmaxf(z, 0.f) + log1pf(expf(-fabsf(z)));
    }
    return v;
}

__device__ __forceinline__ uint32_t pack2bf(float a, float b) {
    __nv_bfloat16 ha = __float2bfloat16(a), hb = __float2bfloat16(b);
    return (uint32_t)__bfloat16_as_ushort(ha) | ((uint32_t)__bfloat16_as_ushort(hb) << 16);
}
__device__ __forceinline__ uint32_t pack2bf_lo(float a, float b) {
    __nv_bfloat16 ha = __float2bfloat16(a), hb = __float2bfloat16(b);
    float ra = a - __bfloat162float(ha), rb = b - __bfloat162float(hb);
    __nv_bfloat16 la = __float2bfloat16(ra), lb = __float2bfloat16(rb);
    return (uint32_t)__bfloat16_as_ushort(la) | ((uint32_t)__bfloat16_as_ushort(lb) << 16);
}

// ---------------- weight split prep ----------------
__global__ void k_prep(const float* __restrict__ W, __nv_bfloat16* __restrict__ hi,
                       __nv_bfloat16* __restrict__ lo, int cnt)
{
    int i = blockIdx.x * blockDim.x + threadIdx.x;
    if (i >= cnt) return;
    float v = W[i];
    __nv_bfloat16 h = __float2bfloat16(v);
    hi[i] = h;
    lo[i] = __float2bfloat16(v - __bfloat162float(h));
}

// ---------------- WMMA GEMM on bf16 hi/lo planes ----------------
// A: either fp32 (APL=false, row stride lda) or planes Ahi/Alo (APL=true, stride lda)
// W: planes Whi/Wlo [KI,KO] tight
// C: fp32 (OPL=false, stride ldc) or planes Chi/Clo (OPL=true, stride ldc)
template <int KI, int KO, int ACT, bool APL, bool OPL>
__global__ __launch_bounds__(256) void wm2(
    const float* __restrict__ Af,
    const __nv_bfloat16* __restrict__ Ahi, const __nv_bfloat16* __restrict__ Alo, int lda,
    const __nv_bfloat16* __restrict__ Whi, const __nv_bfloat16* __restrict__ Wlo,
    const float* __restrict__ bias,
    float* __restrict__ Cf, __nv_bfloat16* __restrict__ Chi, __nv_bfloat16* __restrict__ Clo,
    int ldc, int n)
{
    constexpr int KC  = (KI < 128) ? KI : 128;
    constexpr int NCH = KI / KC;
    constexpr int LDA = KC + 8;
    constexpr int LDW = KO + 8;
    constexpr int NJT = KO / 32;             // col 16-tiles per warp (warp spans KO/2)
    constexpr int AE  = 128 * LDA;
    constexpr int WE  = KC * LDW;

    extern __shared__ char smraw[];
    __nv_bfloat16* sAhi = (__nv_bfloat16*)smraw;
    __nv_bfloat16* sAlo = sAhi + AE;
    __nv_bfloat16* sWhi = sAlo + AE;
    __nv_bfloat16* sWlo = sWhi + WE;

    const int tid  = threadIdx.x;
    const int wid  = tid >> 5;
    const int lane = tid & 31;
    const int rg   = wid >> 1;              // row group 0..3 (32 rows)
    const int cg   = wid & 1;               // col group 0..1 (KO/2 cols)
    const int row0 = blockIdx.x * 128;

    wmma::fragment<wmma::accumulator, 16, 16, 16, float> acc[2][NJT];
#pragma unroll
    for (int i = 0; i < 2; i++)
#pragma unroll
        for (int j = 0; j < NJT; j++) wmma::fill_fragment(acc[i][j], 0.f);

    const uint32_t sAhiB = smem_u32(sAhi);
    const uint32_t sAloB = smem_u32(sAlo);
    const uint32_t sWhiB = smem_u32(sWhi);
    const uint32_t sWloB = smem_u32(sWlo);

    for (int ch = 0; ch < NCH; ch++) {
        if (ch) __syncthreads();
        // ---- A tile into smem ----
        if (APL) {
            constexpr int U = KC / 8;       // 16B units per row
            for (int i = tid; i < 128 * U; i += 256) {
                int r = i / U, u = i % U;
                size_t g = (size_t)(row0 + r) * lda + ch * KC + u * 8;
                uint32_t d = (uint32_t)(r * LDA + u * 8) * 2;
                cpa16(sAhiB + d, Ahi + g);
                cpa16(sAloB + d, Alo + g);
            }
        } else {
            constexpr int Q = KC / 4;
            for (int i = tid; i < 128 * Q; i += 256) {
                int r = i / Q, q = i % Q;
                float4 v = make_float4(0.f, 0.f, 0.f, 0.f);
                if (row0 + r < n)
                    v = *(const float4*)(Af + (size_t)(row0 + r) * lda + ch * KC + 4 * q);
                uint2 hv, lv;
                hv.x = pack2bf(v.x, v.y);    hv.y = pack2bf(v.z, v.w);
                lv.x = pack2bf_lo(v.x, v.y); lv.y = pack2bf_lo(v.z, v.w);
                *(uint2*)(sAhi + r * LDA + 4 * q) = hv;
                *(uint2*)(sAlo + r * LDA + 4 * q) = lv;
            }
        }
        // ---- W chunk into smem ----
        {
            constexpr int U = KO / 8;
            for (int i = tid; i < KC * U; i += 256) {
                int r = i / U, u = i % U;
                size_t g = (size_t)(ch * KC + r) * KO + u * 8;
                uint32_t d = (uint32_t)(r * LDW + u * 8) * 2;
                cpa16(sWhiB + d, Whi + g);
                cpa16(sWloB + d, Wlo + g);
            }
        }
        CPA_COMMIT();
        CPA_WAIT();
        __syncthreads();

        // ---- MMA ----
#pragma unroll
        for (int k = 0; k < KC / 16; k++) {
            wmma::fragment<wmma::matrix_a, 16, 16, 16, __nv_bfloat16, wmma::row_major> ah[2], al[2];
#pragma unroll
            for (int i = 0; i < 2; i++) {
                int r = rg * 32 + i * 16;
                wmma::load_matrix_sync(ah[i], sAhi + r * LDA + k * 16, LDA);
                wmma::load_matrix_sync(al[i], sAlo + r * LDA + k * 16, LDA);
            }
#pragma unroll
            for (int j = 0; j < NJT; j++) {
                int c = cg * (KO / 2) + j * 16;
                wmma::fragment<wmma::matrix_b, 16, 16, 16, __nv_bfloat16, wmma::row_major> bh, bl;
                wmma::load_matrix_sync(bh, sWhi + k * 16 * LDW + c, LDW);
                wmma::load_matrix_sync(bl, sWlo + k * 16 * LDW + c, LDW);
#pragma unroll
                for (int i = 0; i < 2; i++) {
                    wmma::mma_sync(acc[i][j], ah[i], bh, acc[i][j]);
                    wmma::mma_sync(acc[i][j], ah[i], bl, acc[i][j]);
                    wmma::mma_sync(acc[i][j], al[i], bh, acc[i][j]);
                }
            }
        }
    }
    __syncthreads();   // smem reuse as stage

    // ---- epilogue ----
    float* stage = (float*)smraw + wid * 320;   // 16x20 per warp
    const int r8 = lane >> 1;
    const int c8 = (lane & 1) * 8;
#pragma unroll
    for (int i = 0; i < 2; i++) {
        const int grow = row0 + rg * 32 + i * 16 + r8;
#pragma unroll
        for (int j = 0; j < NJT; j++) {
            wmma::store_matrix_sync(stage, acc[i][j], 20, wmma::mem_row_major);
            __syncwarp();
            if (grow < n) {
                const int col = cg * (KO / 2) + j * 16 + c8;
                float o[8];
#pragma unroll
                for (int q = 0; q < 8; q++) {
                    float v = stage[r8 * 20 + c8 + q];
                    if (ACT != 4) v += bias[col + q];
                    o[q] = apply_act<ACT>(v);
                }
                if (OPL) {
                    uint4 hv, lv;
                    hv.x = pack2bf(o[0], o[1]); hv.y = pack2bf(o[2], o[3]);
                    hv.z = pack2bf(o[4], o[5]); hv.w = pack2bf(o[6], o[7]);
                    lv.x = pack2bf_lo(o[0], o[1]); lv.y = pack2bf_lo(o[2], o[3]);
                    lv.z = pack2bf_lo(o[4], o[5]); lv.w = pack2bf_lo(o[6], o[7]);
                    *(uint4*)(Chi + (size_t)grow * ldc + col) = hv;
                    *(uint4*)(Clo + (size_t)grow * ldc + col) = lv;
                } else {
                    float* p = Cf + (size_t)grow * ldc + col;
                    *(float4*)(p + 0) = make_float4(o[0], o[1], o[2], o[3]);
                    *(float4*)(p + 4) = make_float4(o[4], o[5], o[6], o[7]);
                }
            }
            __syncwarp();
        }
    }
}

// ---------------- SIMT GEMM (tiny decoder layers) ----------------
template <int KI, int KO, int ACT, int ROWS>
__global__ __launch_bounds__(256) void gemm_kernel(
    const float* __restrict__ A, const float* __restrict__ W,
    const float* __restrict__ bias, float* __restrict__ C, int n)
{
    constexpr int BC = (KO < 32) ? KO : 32;
    constexpr int BR = 256 / BC;
    constexpr int RT = ROWS / BR;
    constexpr int CT = KO / BC;
    constexpr int KC = (KI < 32) ? KI : 32;

    __shared__ float As[ROWS][KC];
    __shared__ float Ws[KC][KO];
    const int tid = threadIdx.x;
    const int tx = tid % BC;
    const int ty = tid / BC;
    const int row0 = blockIdx.x * ROWS;

    float acc[RT][CT];
#pragma unroll
    for (int i = 0; i < RT; i++)
#pragma unroll
        for (int j = 0; j < CT; j++) acc[i][j] = 0.f;

    for (int k0 = 0; k0 < KI; k0 += KC) {
        if (k0) __syncthreads();
        for (int i = tid; i < KC * KO; i += 256)
            Ws[i / KO][i % KO] = W[(size_t)k0 * KO + i];
        for (int i = tid; i < ROWS * KC; i += 256) {
            int r = i / KC, kk = i % KC;
            int gr = row0 + r;
            As[r][kk] = (gr < n) ? A[(size_t)gr * KI + k0 + kk] : 0.f;
        }
        __syncthreads();
#pragma unroll
        for (int kk = 0; kk < KC; kk++) {
            float av[RT], wv[CT];
#pragma unroll
            for (int i = 0; i < RT; i++) av[i] = As[ty * RT + i][kk];
#pragma unroll
            for (int j = 0; j < CT; j++) wv[j] = Ws[kk][j * BC + tx];
#pragma unroll
            for (int i = 0; i < RT; i++)
#pragma unroll
                for (int j = 0; j < CT; j++) acc[i][j] += av[i] * wv[j];
        }
    }
#pragma unroll
    for (int j = 0; j < CT; j++) {
        int col = j * BC + tx;
        float bv = bias[col];
#pragma unroll
        for (int i = 0; i < RT; i++) {
            int r = row0 + ty * RT + i;
            if (r < n) C[(size_t)r * KO + col] = apply_act<ACT>(acc[i][j] + bv);
        }
    }
}

// ---------------- degree / dinv ----------------
__global__ void k_deg_init(float* dinv, int n) {
    int i = blockIdx.x * blockDim.x + threadIdx.x;
    if (i < n) dinv[i] = 1.f;
}
__global__ void k_deg_acc(const int* __restrict__ dst, float* dinv, int E) {
    int i = blockIdx.x * blockDim.x + threadIdx.x;
    if (i < E) atomicAdd(&dinv[dst[i]], 1.f);
}
__global__ void k_deg_fin(float* dinv, int n) {
    int i = blockIdx.x * blockDim.x + threadIdx.x;
    if (i < n) dinv[i] = rsqrtf(dinv[i]);
}

// ---------------- GCN scatter ----------------
__global__ void k_scatter_init(const float* __restrict__ g, const float* __restrict__ dinv,
                               const float* __restrict__ bias, float* __restrict__ o, int n)
{
    int i = blockIdx.x * blockDim.x + threadIdx.x;
    if (i >= n * 32) return;
    int node = i >> 5;
    int c4 = (i & 31) * 4;
    float dv = dinv[node];
    float s = dv * dv;
    float4 v = *(const float4*)(g + (size_t)node * 128 + c4);
    float4 r;
    r.x = v.x * s + bias[c4 + 0];
    r.y = v.y * s + bias[c4 + 1];
    r.z = v.z * s + bias[c4 + 2];
    r.w = v.w * s + bias[c4 + 3];
    *(float4*)(o + (size_t)node * 128 + c4) = r;
}

__global__ void k_scatter_edges(const int* __restrict__ src, const int* __restrict__ dst,
                                const float* __restrict__ dinv, const float* __restrict__ g,
                                float* __restrict__ o, int E)
{
    int t = blockIdx.x * blockDim.x + threadIdx.x;
    int e = t >> 5;
    if (e >= E) return;
    int lane = t & 31;
    int s = 0, d = 0;
    float w = 0.f;
    if (lane == 0) {
        s = src[e];
        d = dst[e];
        w = dinv[s] * dinv[d];
    }
    s = __shfl_sync(0xffffffffu, s, 0);
    d = __shfl_sync(0xffffffffu, d, 0);
    w = __shfl_sync(0xffffffffu, w, 0);
    float4 v = *(const float4*)(g + (size_t)s * 128 + lane * 4);
    float* p = o + (size_t)d * 128 + lane * 4;
    asm volatile("red.global.add.v4.f32 [%0], {%1, %2, %3, %4};"
                 :: "l"(p), "f"(v.x * w), "f"(v.y * w), "f"(v.z * w), "f"(v.w * w)
                 : "memory");
}

// ---------------- reparametrization: h planes = mu + std*eps ----------------
__global__ void k_hupdate(const float* __restrict__ mu, const float* __restrict__ sd,
                          const float* __restrict__ eps,
                          __nv_bfloat16* __restrict__ hhi, __nv_bfloat16* __restrict__ hlo,
                          int cnt4)
{
    int i = blockIdx.x * blockDim.x + threadIdx.x;
    if (i >= cnt4) return;
    float4 m = ((const float4*)mu)[i];
    float4 s = ((const float4*)sd)[i];
    float4 e = ((const float4*)eps)[i];
    float h0 = m.x + s.x * e.x, h1 = m.y + s.y * e.y;
    float h2 = m.z + s.z * e.z, h3 = m.w + s.w * e.w;
    uint2 hv, lv;
    hv.x = pack2bf(h0, h1);    hv.y = pack2bf(h2, h3);
    lv.x = pack2bf_lo(h0, h1); lv.y = pack2bf_lo(h2, h3);
    *(uint2*)(hhi + (size_t)i * 4) = hv;
    *(uint2*)(hlo + (size_t)i * 4) = lv;
}

// ---------------- final 16 -> 10 ----------------
__global__ void k_final10(const float* __restrict__ A, const float* __restrict__ Wo,
                          const float* __restrict__ bo, float* __restrict__ yp, int n)
{
    __shared__ float w[160];
    __shared__ float bb[10];
    if (threadIdx.x < 160) w[threadIdx.x] = Wo[threadIdx.x];
    if (threadIdx.x < 10) bb[threadIdx.x] = bo[threadIdx.x];
    __syncthreads();
    int i = blockIdx.x * blockDim.x + threadIdx.x;
    if (i >= n) return;
    float a[16];
#pragma unroll
    for (int k = 0; k < 16; k++) a[k] = A[(size_t)i * 16 + k];
#pragma unroll
    for (int c = 0; c < 10; c++) {
        float s = bb[c];
#pragma unroll
        for (int k = 0; k < 16; k++) s += a[k] * w[k * 10 + c];
        yp[(size_t)i * 10 + c] = 1.f / (1.f + expf(-s));
    }
}

// ---------------- pooling ----------------
__global__ void k_pool_init(float* sums, float* cnt, int gsz) {
    int i = blockIdx.x * blockDim.x + threadIdx.x;
    if (i < gsz * 10) sums[i] = 0.f;
    if (i < gsz) cnt[i] = 0.f;
}
__global__ void k_pool_acc(const float* __restrict__ yp, const int* __restrict__ bids,
                           float* sums, float* cnt, int n)
{
    int i = blockIdx.x * blockDim.x + threadIdx.x;
    if (i >= n) return;
    int b = bids[i];
    const float* r = yp + (size_t)i * 10;
#pragma unroll
    for (int c = 0; c < 10; c++) atomicAdd(&sums[b * 10 + c], r[c]);
    atomicAdd(&cnt[b], 1.f);
}
__global__ void k_pool_fin(const float* __restrict__ sums, const float* __restrict__ cnt,
                           const float* __restrict__ y, float* __restrict__ out,
                           float* __restrict__ yout, int tot)
{
    int i = blockIdx.x * blockDim.x + threadIdx.x;
    if (i >= tot) return;
    out[i] = sums[i] / fmaxf(cnt[i / 10], 1.f);
    yout[i] = y[i];
}

// ---------------- host helpers ----------------
template <int KI, int KO, int ACT, bool APL, bool OPL>
static void run2(const float* Af, const __nv_bfloat16* Ahi, const __nv_bfloat16* Alo, int lda,
                 const __nv_bfloat16* Whi, const __nv_bfloat16* Wlo, const float* bias,
                 float* Cf, __nv_bfloat16* Chi, __nv_bfloat16* Clo, int ldc, int n)
{
    constexpr int KC = (KI < 128) ? KI : 128;
    constexpr int SMB = (128 * (KC + 8) + KC * (KO + 8)) * 2 * 2;
    cudaFuncSetAttribute(wm2<KI, KO, ACT, APL, OPL>,
                         cudaFuncAttributeMaxDynamicSharedMemorySize, SMB);
    wm2<KI, KO, ACT, APL, OPL><<<(n + 127) / 128, 256, SMB>>>(
        Af, Ahi, Alo, lda, Whi, Wlo, bias, Cf, Chi, Clo, ldc, n);
}

extern "C" void kernel_launch(void* const* d_in, const int* in_sizes, int n_in,
                              void* d_out, int out_size)
{
    const float* x     = (const float*)d_in[0];
    const int*   ei    = (const int*)d_in[1];
    const int*   bids  = (const int*)d_in[2];
    const float* y     = (const float*)d_in[3];
    const float* eps   = (const float*)d_in[4];
    const float* W_in  = (const float*)d_in[5];
    const float* b_in  = (const float*)d_in[6];
    const float* W_gcn = (const float*)d_in[7];
    const float* b_gcn = (const float*)d_in[8];
    const float* W_enc = (const float*)d_in[9];
    const float* b_enc = (const float*)d_in[10];
    const float* W_mu  = (const float*)d_in[11];
    const float* b_mu  = (const float*)d_in[12];
    const float* W_std = (const float*)d_in[13];
    const float* b_std = (const float*)d_in[14];
    const float* Wd0 = (const float*)d_in[15]; const float* bd0 = (const float*)d_in[16];
    const float* Wd1 = (const float*)d_in[17]; const float* bd1 = (const float*)d_in[18];
    const float* Wd2 = (const float*)d_in[19]; const float* bd2 = (const float*)d_in[20];
    const float* Wd3 = (const float*)d_in[21]; const float* bd3 = (const float*)d_in[22];
    const float* Wd4 = (const float*)d_in[23]; const float* bd4 = (const float*)d_in[24];
    const float* Wo  = (const float*)d_in[25]; const float* bo  = (const float*)d_in[26];

    const int N = in_sizes[2];
    const int E = in_sizes[1] / 2;
    const int G = in_sizes[3] / 10;
    const int* src = ei;
    const int* dst = ei + E;

    float *dinv, *a, *b, *yp, *sums, *cnt;
    __nv_bfloat16 *hhi, *hlo, *p0hi, *p0lo, *p1hi, *p1lo, *whi, *wlo;
    cudaGetSymbolAddress((void**)&dinv, g_dinv);
    cudaGetSymbolAddress((void**)&a,    g_a);
    cudaGetSymbolAddress((void**)&b,    g_b);
    cudaGetSymbolAddress((void**)&yp,   g_yp);
    cudaGetSymbolAddress((void**)&sums, g_sums);
    cudaGetSymbolAddress((void**)&cnt,  g_cnt);
    cudaGetSymbolAddress((void**)&hhi,  g_hhi);
    cudaGetSymbolAddress((void**)&hlo,  g_hlo);
    cudaGetSymbolAddress((void**)&p0hi, g_p0hi);
    cudaGetSymbolAddress((void**)&p0lo, g_p0lo);
    cudaGetSymbolAddress((void**)&p1hi, g_p1hi);
    cudaGetSymbolAddress((void**)&p1lo, g_p1lo);
    cudaGetSymbolAddress((void**)&whi,  g_whi);
    cudaGetSymbolAddress((void**)&wlo,  g_wlo);

    float* out    = (float*)d_out;
    float* mu_out = out + (size_t)G * 10;
    float* sd_out = mu_out + (size_t)N * 128;
    float* y_out  = sd_out + (size_t)N * 128;

    const int TB = 256;
    const int gb128 = (N + 127) / 128;

    // ---- weight split prep ----
    k_prep<<<(4096 + 255) / 256, 256>>>(W_in,  whi + WOFF_IN,  wlo + WOFF_IN,  4096);
    k_prep<<<(16384 + 255) / 256, 256>>>(W_gcn, whi + WOFF_GCN, wlo + WOFF_GCN, 16384);
    k_prep<<<(81920 + 255) / 256, 256>>>(W_enc, whi + WOFF_ENC, wlo + WOFF_ENC, 81920);
    k_prep<<<(16384 + 255) / 256, 256>>>(W_mu,  whi + WOFF_MU,  wlo + WOFF_MU,  16384);
    k_prep<<<(16384 + 255) / 256, 256>>>(W_std, whi + WOFF_STD, wlo + WOFF_STD, 16384);
    k_prep<<<(32768 + 255) / 256, 256>>>(Wd0,   whi + WOFF_D0,  wlo + WOFF_D0,  32768);
    k_prep<<<(32768 + 255) / 256, 256>>>(Wd1,   whi + WOFF_D1,  wlo + WOFF_D1,  32768);
    k_prep<<<(8192 + 255) / 256, 256>>>(Wd2,   whi + WOFF_D2,  wlo + WOFF_D2,  8192);

    // ---- degrees ----
    k_deg_init<<<(N + TB - 1) / TB, TB>>>(dinv, N);
    k_deg_acc<<<(E + TB - 1) / TB, TB>>>(dst, dinv, E);
    k_deg_fin<<<(N + TB - 1) / TB, TB>>>(dinv, N);

    // ---- input layer: x fp32 -> h planes ----
    run2<32, 128, 1, false, true>(x, nullptr, nullptr, 32,
                                  whi + WOFF_IN, wlo + WOFF_IN, b_in,
                                  nullptr, hhi, hlo, 128, N);

    for (int hop = 0; hop < 3; hop++) {
        // gcn: h planes -> fp32 a
        run2<128, 128, 4, true, false>(nullptr, hhi, hlo, 128,
                                       whi + WOFF_GCN, wlo + WOFF_GCN, nullptr,
                                       a, nullptr, nullptr, 128, N);
        k_scatter_init<<<((size_t)N * 32 + TB - 1) / TB, TB>>>(a, dinv, b_gcn, b, N);
        k_scatter_edges<<<((size_t)E * 32 + TB - 1) / TB, TB>>>(src, dst, dinv, a, b, E);
        // enc0: fp32 b -> p0 planes
        run2<128, 128, 1, false, true>(b, nullptr, nullptr, 128,
                                       whi + WOFF_ENC + 0 * 16384, wlo + WOFF_ENC + 0 * 16384,
                                       b_enc + 0 * 128, nullptr, p0hi, p0lo, 128, N);
        run2<128, 128, 1, true, true>(nullptr, p0hi, p0lo, 128,
                                      whi + WOFF_ENC + 1 * 16384, wlo + WOFF_ENC + 1 * 16384,
                                      b_enc + 1 * 128, nullptr, p1hi, p1lo, 128, N);
        run2<128, 128, 1, true, true>(nullptr, p1hi, p1lo, 128,
                                      whi + WOFF_ENC + 2 * 16384, wlo + WOFF_ENC + 2 * 16384,
                                      b_enc + 2 * 128, nullptr, p0hi, p0lo, 128, N);
        run2<128, 128, 1, true, true>(nullptr, p0hi, p0lo, 128,
                                      whi + WOFF_ENC + 3 * 16384, wlo + WOFF_ENC + 3 * 16384,
                                      b_enc + 3 * 128, nullptr, p1hi, p1lo, 128, N);
        run2<128, 128, 1, true, true>(nullptr, p1hi, p1lo, 128,
                                      whi + WOFF_ENC + 4 * 16384, wlo + WOFF_ENC + 4 * 16384,
                                      b_enc + 4 * 128, nullptr, p0hi, p0lo, 128, N);
        // mu / std: p0 planes -> fp32 outputs
        run2<128, 128, 0, true, false>(nullptr, p0hi, p0lo, 128,
                                       whi + WOFF_MU, wlo + WOFF_MU, b_mu,
                                       mu_out, nullptr, nullptr, 128, N);
        run2<128, 128, 3, true, false>(nullptr, p0hi, p0lo, 128,
                                       whi + WOFF_STD, wlo + WOFF_STD, b_std,
                                       sd_out, nullptr, nullptr, 128, N);
        k_hupdate<<<((size_t)N * 32 + TB - 1) / TB, TB>>>(mu_out, sd_out,
                                                          eps + (size_t)hop * N * 128,
                                                          hhi, hlo, N * 32);
    }

    // ---- decoder ----
    // d0: h planes -> p1 planes [N,256] in two column halves
    run2<128, 128, 2, true, true>(nullptr, hhi, hlo, 128,
                                  whi + WOFF_D0, wlo + WOFF_D0, bd0,
                                  nullptr, p1hi, p1lo, 256, N);
    run2<128, 128, 2, true, true>(nullptr, hhi, hlo, 128,
                                  whi + WOFF_D0 + 128, wlo + WOFF_D0 + 128, bd0 + 128,
                                  nullptr, p1hi + 128, p1lo + 128, 256, N);
    // d1: p1 planes (KI=256) -> p0 planes
    run2<256, 128, 2, true, true>(nullptr, p1hi, p1lo, 256,
                                  whi + WOFF_D1, wlo + WOFF_D1, bd1,
                                  nullptr, p0hi, p0lo, 128, N);
    // d2: p0 planes -> fp32 b [N,64]
    run2<128, 64, 2, true, false>(nullptr, p0hi, p0lo, 128,
                                  whi + WOFF_D2, wlo + WOFF_D2, bd2,
                                  b, nullptr, nullptr, 64, N);
    gemm_kernel<64, 32, 2, 128><<<gb128, TB>>>(b, Wd3, bd3, a, N);
    gemm_kernel<32, 16, 2, 128><<<gb128, TB>>>(a, Wd4, bd4, b, N);
    k_final10<<<(N + TB - 1) / TB, TB>>>(b, Wo, bo, yp, N);

    // ---- pooling ----
    k_pool_init<<<(G * 10 + TB - 1) / TB, TB>>>(sums, cnt, G);
    k_pool_acc<<<(N + TB - 1) / TB, TB>>>(yp, bids, sums, cnt, N);
    k_pool_fin<<<(G * 10 + TB - 1) / TB, TB>>>(sums, cnt, y, out, y_out, G * 10);
}

// round 6
// speedup vs baseline: 1.7810x; 1.0418x over previous
#include <cuda_runtime.h>
#include <cuda_bf16.h>
#include <mma.h>
#include <math.h>
#include <stdint.h>

using namespace nvcuda;

#define MAXN  50000
#define NPAD  50176

// ---------------- device scratch ----------------
__device__ float g_dinv[MAXN];
__device__ float g_a[(size_t)MAXN * 128];
__device__ float g_b[(size_t)MAXN * 256];
__device__ float g_yp[(size_t)MAXN * 10];
__device__ float g_sums[256 * 10];
__device__ float g_cnt[256];

__device__ __nv_bfloat16 g_hhi[(size_t)NPAD * 128];
__device__ __nv_bfloat16 g_hlo[(size_t)NPAD * 128];
__device__ __nv_bfloat16 g_p0hi[(size_t)NPAD * 256];
__device__ __nv_bfloat16 g_p0lo[(size_t)NPAD * 256];
__device__ __nv_bfloat16 g_p1hi[(size_t)NPAD * 256];
__device__ __nv_bfloat16 g_p1lo[(size_t)NPAD * 256];

#define WOFF_IN  0
#define WOFF_GCN 4096
#define WOFF_ENC 20480
#define WOFF_MU  102400
#define WOFF_STD 118784
#define WOFF_D0  135168
#define WOFF_D1  167936
#define WOFF_D2  200704
#define WTOT     208896
__device__ __nv_bfloat16 g_whi[WTOT];
__device__ __nv_bfloat16 g_wlo[WTOT];

// ---------------- helpers ----------------
__device__ __forceinline__ uint32_t smem_u32(const void* p) {
    uint32_t a;
    asm("{ .reg .u64 t; cvta.to.shared.u64 t, %1; cvt.u32.u64 %0, t; }" : "=r"(a) : "l"(p));
    return a;
}
__device__ __forceinline__ void cpa16(uint32_t dst, const void* src) {
    asm volatile("cp.async.ca.shared.global [%0], [%1], 16;" :: "r"(dst), "l"(src));
}
#define CPA_COMMIT() asm volatile("cp.async.commit_group;" ::: "memory")
#define CPA_WAIT()   asm volatile("cp.async.wait_group 0;" ::: "memory")

// ACT: 0 lin+bias, 1 sigmoid, 2 relu, 3 softplus(v-5), 4 lin no-bias, 5 gcn-split
template <int ACT>
__device__ __forceinline__ float apply_act(float v) {
    if (ACT == 1) return 1.f / (1.f + expf(-v));
    if (ACT == 2) return fmaxf(v, 0.f);
    if (ACT == 3) {
        float z = v - 5.f;
        return fmaxf(z, 0.f) + log1pf(expf(-fabsf(z)));
    }
    return v;
}

__device__ __forceinline__ uint32_t pack2bf(float a, float b) {
    __nv_bfloat16 ha = __float2bfloat16(a), hb = __float2bfloat16(b);
    return (uint32_t)__bfloat16_as_ushort(ha) | ((uint32_t)__bfloat16_as_ushort(hb) << 16);
}
__device__ __forceinline__ uint32_t pack2bf_lo(float a, float b) {
    __nv_bfloat16 ha = __float2bfloat16(a), hb = __float2bfloat16(b);
    float ra = a - __bfloat162float(ha), rb = b - __bfloat162float(hb);
    __nv_bfloat16 la = __float2bfloat16(ra), lb = __float2bfloat16(rb);
    return (uint32_t)__bfloat16_as_ushort(la) | ((uint32_t)__bfloat16_as_ushort(lb) << 16);
}

// ---------------- one-launch weight split prep ----------------
struct PrepSrc { const float* s[8]; };
__constant__ int c_woff[9] = {WOFF_IN, WOFF_GCN, WOFF_ENC, WOFF_MU, WOFF_STD,
                              WOFF_D0, WOFF_D1, WOFF_D2, WTOT};
__global__ void k_prep_all(PrepSrc ps, __nv_bfloat16* __restrict__ hi,
                           __nv_bfloat16* __restrict__ lo)
{
    int i = blockIdx.x * blockDim.x + threadIdx.x;
    if (i >= WTOT) return;
    int r = 0;
#pragma unroll
    for (int k = 1; k < 8; k++) if (i >= c_woff[k]) r = k;
    float v = ps.s[r][i - c_woff[r]];
    __nv_bfloat16 h = __float2bfloat16(v);
    hi[i] = h;
    lo[i] = __float2bfloat16(v - __bfloat162float(h));
}

// ---------------- WMMA GEMM on bf16 hi/lo planes ----------------
template <int KI, int KO, int ACT, bool APL, bool OPL>
__global__ __launch_bounds__(256) void wm2(
    const float* __restrict__ Af,
    const __nv_bfloat16* __restrict__ Ahi, const __nv_bfloat16* __restrict__ Alo, int lda,
    const __nv_bfloat16* __restrict__ Whi, const __nv_bfloat16* __restrict__ Wlo,
    const float* __restrict__ bias,
    float* __restrict__ Cf, __nv_bfloat16* __restrict__ Chi, __nv_bfloat16* __restrict__ Clo,
    int ldc, int n,
    const float* __restrict__ dinv, float* __restrict__ Cf2)
{
    constexpr int KC  = (KI < 128) ? KI : 128;
    constexpr int NCH = KI / KC;
    constexpr int LDA = KC + 8;
    constexpr int LDW = KO + 8;
    constexpr int NJT = KO / 32;
    constexpr int AE  = 128 * LDA;
    constexpr int WE  = KC * LDW;

    extern __shared__ char smraw[];
    __nv_bfloat16* sAhi = (__nv_bfloat16*)smraw;
    __nv_bfloat16* sAlo = sAhi + AE;
    __nv_bfloat16* sWhi = sAlo + AE;
    __nv_bfloat16* sWlo = sWhi + WE;

    const int tid  = threadIdx.x;
    const int wid  = tid >> 5;
    const int lane = tid & 31;
    const int rg   = wid >> 1;
    const int cg   = wid & 1;
    const int row0 = blockIdx.x * 128;

    wmma::fragment<wmma::accumulator, 16, 16, 16, float> acc[2][NJT];
#pragma unroll
    for (int i = 0; i < 2; i++)
#pragma unroll
        for (int j = 0; j < NJT; j++) wmma::fill_fragment(acc[i][j], 0.f);

    const uint32_t sAhiB = smem_u32(sAhi);
    const uint32_t sAloB = smem_u32(sAlo);
    const uint32_t sWhiB = smem_u32(sWhi);
    const uint32_t sWloB = smem_u32(sWlo);

    for (int ch = 0; ch < NCH; ch++) {
        if (ch) __syncthreads();
        if (APL) {
            constexpr int U = KC / 8;
            for (int i = tid; i < 128 * U; i += 256) {
                int r = i / U, u = i % U;
                size_t g = (size_t)(row0 + r) * lda + ch * KC + u * 8;
                uint32_t d = (uint32_t)(r * LDA + u * 8) * 2;
                cpa16(sAhiB + d, Ahi + g);
                cpa16(sAloB + d, Alo + g);
            }
        } else {
            constexpr int Q = KC / 4;
            for (int i = tid; i < 128 * Q; i += 256) {
                int r = i / Q, q = i % Q;
                float4 v = make_float4(0.f, 0.f, 0.f, 0.f);
                if (row0 + r < n)
                    v = *(const float4*)(Af + (size_t)(row0 + r) * lda + ch * KC + 4 * q);
                uint2 hv, lv;
                hv.x = pack2bf(v.x, v.y);    hv.y = pack2bf(v.z, v.w);
                lv.x = pack2bf_lo(v.x, v.y); lv.y = pack2bf_lo(v.z, v.w);
                *(uint2*)(sAhi + r * LDA + 4 * q) = hv;
                *(uint2*)(sAlo + r * LDA + 4 * q) = lv;
            }
        }
        {
            constexpr int U = KO / 8;
            for (int i = tid; i < KC * U; i += 256) {
                int r = i / U, u = i % U;
                size_t g = (size_t)(ch * KC + r) * KO + u * 8;
                uint32_t d = (uint32_t)(r * LDW + u * 8) * 2;
                cpa16(sWhiB + d, Whi + g);
                cpa16(sWloB + d, Wlo + g);
            }
        }
        CPA_COMMIT();
        CPA_WAIT();
        __syncthreads();

#pragma unroll
        for (int k = 0; k < KC / 16; k++) {
            wmma::fragment<wmma::matrix_a, 16, 16, 16, __nv_bfloat16, wmma::row_major> ah[2], al[2];
#pragma unroll
            for (int i = 0; i < 2; i++) {
                int r = rg * 32 + i * 16;
                wmma::load_matrix_sync(ah[i], sAhi + r * LDA + k * 16, LDA);
                wmma::load_matrix_sync(al[i], sAlo + r * LDA + k * 16, LDA);
            }
#pragma unroll
            for (int j = 0; j < NJT; j++) {
                int c = cg * (KO / 2) + j * 16;
                wmma::fragment<wmma::matrix_b, 16, 16, 16, __nv_bfloat16, wmma::row_major> bh, bl;
                wmma::load_matrix_sync(bh, sWhi + k * 16 * LDW + c, LDW);
                wmma::load_matrix_sync(bl, sWlo + k * 16 * LDW + c, LDW);
#pragma unroll
                for (int i = 0; i < 2; i++) {
                    wmma::mma_sync(acc[i][j], ah[i], bh, acc[i][j]);
                    wmma::mma_sync(acc[i][j], ah[i], bl, acc[i][j]);
                    wmma::mma_sync(acc[i][j], al[i], bh, acc[i][j]);
                }
            }
        }
    }
    __syncthreads();

    float* stage = (float*)smraw + wid * 320;
    const int r8 = lane >> 1;
    const int c8 = (lane & 1) * 8;
#pragma unroll
    for (int i = 0; i < 2; i++) {
        const int grow = row0 + rg * 32 + i * 16 + r8;
#pragma unroll
        for (int j = 0; j < NJT; j++) {
            wmma::store_matrix_sync(stage, acc[i][j], 20, wmma::mem_row_major);
            __syncwarp();
            if (grow < n) {
                const int col = cg * (KO / 2) + j * 16 + c8;
                if (ACT == 5) {
                    float dv = dinv[grow];
                    float sc = dv * dv;
                    float raw[8], ini[8];
#pragma unroll
                    for (int q = 0; q < 8; q++) {
                        raw[q] = stage[r8 * 20 + c8 + q];
                        ini[q] = raw[q] * sc + bias[col + q];
                    }
                    float* p1 = Cf + (size_t)grow * ldc + col;
                    float* p2 = Cf2 + (size_t)grow * ldc + col;
                    *(float4*)(p1 + 0) = make_float4(raw[0], raw[1], raw[2], raw[3]);
                    *(float4*)(p1 + 4) = make_float4(raw[4], raw[5], raw[6], raw[7]);
                    *(float4*)(p2 + 0) = make_float4(ini[0], ini[1], ini[2], ini[3]);
                    *(float4*)(p2 + 4) = make_float4(ini[4], ini[5], ini[6], ini[7]);
                } else {
                    float o[8];
#pragma unroll
                    for (int q = 0; q < 8; q++) {
                        float v = stage[r8 * 20 + c8 + q];
                        if (ACT != 4) v += bias[col + q];
                        o[q] = apply_act<ACT>(v);
                    }
                    if (OPL) {
                        uint4 hv, lv;
                        hv.x = pack2bf(o[0], o[1]); hv.y = pack2bf(o[2], o[3]);
                        hv.z = pack2bf(o[4], o[5]); hv.w = pack2bf(o[6], o[7]);
                        lv.x = pack2bf_lo(o[0], o[1]); lv.y = pack2bf_lo(o[2], o[3]);
                        lv.z = pack2bf_lo(o[4], o[5]); lv.w = pack2bf_lo(o[6], o[7]);
                        *(uint4*)(Chi + (size_t)grow * ldc + col) = hv;
                        *(uint4*)(Clo + (size_t)grow * ldc + col) = lv;
                    } else {
                        float* p = Cf + (size_t)grow * ldc + col;
                        *(float4*)(p + 0) = make_float4(o[0], o[1], o[2], o[3]);
                        *(float4*)(p + 4) = make_float4(o[4], o[5], o[6], o[7]);
                    }
                }
            }
            __syncwarp();
        }
    }
}

// ---------------- fused encoder block: enc0..4 + mu + std + reparam ----------------
// smem: sA planes (128x136 x2), sW planes (128x136 x2), sMu fp32 128x132, stage
#define EF_LDA 136
#define EF_AE  (128 * EF_LDA)
#define EF_SMEM (4 * EF_AE * 2 + 128 * 132 * 4 + 8 * 320 * 4)

__global__ __launch_bounds__(256) void enc_fused(
    const float* __restrict__ B,
    const __nv_bfloat16* __restrict__ whi, const __nv_bfloat16* __restrict__ wlo,
    const float* __restrict__ b_enc, const float* __restrict__ b_mu,
    const float* __restrict__ b_std, const float* __restrict__ eps,
    __nv_bfloat16* __restrict__ hhi, __nv_bfloat16* __restrict__ hlo,
    float* __restrict__ mu_out, float* __restrict__ sd_out, int write_musd, int n)
{
    extern __shared__ char smraw[];
    __nv_bfloat16* sAhi = (__nv_bfloat16*)smraw;
    __nv_bfloat16* sAlo = sAhi + EF_AE;
    __nv_bfloat16* sWhi = sAlo + EF_AE;
    __nv_bfloat16* sWlo = sWhi + EF_AE;
    float* sMu   = (float*)(sWlo + EF_AE);
    float* stageB = sMu + 128 * 132;

    const int tid  = threadIdx.x;
    const int wid  = tid >> 5;
    const int lane = tid & 31;
    const int rg   = wid >> 1;
    const int cg   = wid & 1;
    const int row0 = blockIdx.x * 128;
    const int r8   = lane >> 1;
    const int c8   = (lane & 1) * 8;
    float* stage = stageB + wid * 320;

    const uint32_t sWhiB = smem_u32(sWhi);
    const uint32_t sWloB = smem_u32(sWlo);

    // ---- load input (fp32) -> sA planes ----
    for (int i = tid; i < 128 * 32; i += 256) {
        int r = i >> 5, q = i & 31;
        float4 v = make_float4(0.f, 0.f, 0.f, 0.f);
        if (row0 + r < n)
            v = *(const float4*)(B + (size_t)(row0 + r) * 128 + 4 * q);
        uint2 hv, lv;
        hv.x = pack2bf(v.x, v.y);    hv.y = pack2bf(v.z, v.w);
        lv.x = pack2bf_lo(v.x, v.y); lv.y = pack2bf_lo(v.z, v.w);
        *(uint2*)(sAhi + r * EF_LDA + 4 * q) = hv;
        *(uint2*)(sAlo + r * EF_LDA + 4 * q) = lv;
    }

    for (int l = 0; l < 7; l++) {
        // ---- layer weights ----
        int woff = (l < 5) ? (WOFF_ENC + l * 16384) : ((l == 5) ? WOFF_MU : WOFF_STD);
        const __nv_bfloat16* Wh = whi + woff;
        const __nv_bfloat16* Wl = wlo + woff;
        for (int i = tid; i < 128 * 16; i += 256) {
            int r = i >> 4, u = i & 15;
            uint32_t d = (uint32_t)(r * EF_LDA + u * 8) * 2;
            cpa16(sWhiB + d, Wh + r * 128 + u * 8);
            cpa16(sWloB + d, Wl + r * 128 + u * 8);
        }
        CPA_COMMIT();
        CPA_WAIT();
        __syncthreads();   // weights visible + sA writes from prev layer visible

        // ---- MMA ----
        wmma::fragment<wmma::accumulator, 16, 16, 16, float> acc[2][4];
#pragma unroll
        for (int i = 0; i < 2; i++)
#pragma unroll
            for (int j = 0; j < 4; j++) wmma::fill_fragment(acc[i][j], 0.f);
#pragma unroll
        for (int k = 0; k < 8; k++) {
            wmma::fragment<wmma::matrix_a, 16, 16, 16, __nv_bfloat16, wmma::row_major> ah[2], al[2];
#pragma unroll
            for (int i = 0; i < 2; i++) {
                int r = rg * 32 + i * 16;
                wmma::load_matrix_sync(ah[i], sAhi + r * EF_LDA + k * 16, EF_LDA);
                wmma::load_matrix_sync(al[i], sAlo + r * EF_LDA + k * 16, EF_LDA);
            }
#pragma unroll
            for (int j = 0; j < 4; j++) {
                int c = cg * 64 + j * 16;
                wmma::fragment<wmma::matrix_b, 16, 16, 16, __nv_bfloat16, wmma::row_major> bh, bl;
                wmma::load_matrix_sync(bh, sWhi + k * 16 * EF_LDA + c, EF_LDA);
                wmma::load_matrix_sync(bl, sWlo + k * 16 * EF_LDA + c, EF_LDA);
#pragma unroll
                for (int i = 0; i < 2; i++) {
                    wmma::mma_sync(acc[i][j], ah[i], bh, acc[i][j]);
                    wmma::mma_sync(acc[i][j], ah[i], bl, acc[i][j]);
                    wmma::mma_sync(acc[i][j], al[i], bh, acc[i][j]);
                }
            }
        }
        __syncthreads();   // all MMA reads of sA/sW complete

        // ---- epilogue ----
#pragma unroll
        for (int i = 0; i < 2; i++) {
            const int lrow = rg * 32 + i * 16 + r8;
            const int grow = row0 + lrow;
#pragma unroll
            for (int j = 0; j < 4; j++) {
                wmma::store_matrix_sync(stage, acc[i][j], 20, wmma::mem_row_major);
                __syncwarp();
                const int col = cg * 64 + j * 16 + c8;
                if (l < 5) {
                    // sigmoid, write back to sA planes
                    float o[8];
#pragma unroll
                    for (int q = 0; q < 8; q++) {
                        float v = stage[r8 * 20 + c8 + q] + b_enc[l * 128 + col + q];
                        o[q] = 1.f / (1.f + expf(-v));
                    }
                    uint4 hv, lv;
                    hv.x = pack2bf(o[0], o[1]); hv.y = pack2bf(o[2], o[3]);
                    hv.z = pack2bf(o[4], o[5]); hv.w = pack2bf(o[6], o[7]);
                    lv.x = pack2bf_lo(o[0], o[1]); lv.y = pack2bf_lo(o[2], o[3]);
                    lv.z = pack2bf_lo(o[4], o[5]); lv.w = pack2bf_lo(o[6], o[7]);
                    *(uint4*)(sAhi + lrow * EF_LDA + col) = hv;
                    *(uint4*)(sAlo + lrow * EF_LDA + col) = lv;
                } else if (l == 5) {
                    // mu: stash in sMu (+ optional gmem)
                    float o[8];
#pragma unroll
                    for (int q = 0; q < 8; q++) {
                        o[q] = stage[r8 * 20 + c8 + q] + b_mu[col + q];
                        sMu[lrow * 132 + col + q] = o[q];
                    }
                    if (write_musd && grow < n) {
                        float* p = mu_out + (size_t)grow * 128 + col;
                        *(float4*)(p + 0) = make_float4(o[0], o[1], o[2], o[3]);
                        *(float4*)(p + 4) = make_float4(o[4], o[5], o[6], o[7]);
                    }
                } else {
                    // std: softplus, h = mu + std*eps -> h planes
                    float s[8], h[8];
                    float4 e0 = make_float4(0.f, 0.f, 0.f, 0.f), e1 = e0;
                    if (grow < n) {
                        e0 = *(const float4*)(eps + (size_t)grow * 128 + col);
                        e1 = *(const float4*)(eps + (size_t)grow * 128 + col + 4);
                    }
                    float ev[8] = {e0.x, e0.y, e0.z, e0.w, e1.x, e1.y, e1.z, e1.w};
#pragma unroll
                    for (int q = 0; q < 8; q++) {
                        float z = stage[r8 * 20 + c8 + q] + b_std[col + q] - 5.f;
                        s[q] = fmaxf(z, 0.f) + log1pf(expf(-fabsf(z)));
                        h[q] = sMu[lrow * 132 + col + q] + s[q] * ev[q];
                    }
                    if (grow < n) {
                        uint4 hv, lv;
                        hv.x = pack2bf(h[0], h[1]); hv.y = pack2bf(h[2], h[3]);
                        hv.z = pack2bf(h[4], h[5]); hv.w = pack2bf(h[6], h[7]);
                        lv.x = pack2bf_lo(h[0], h[1]); lv.y = pack2bf_lo(h[2], h[3]);
                        lv.z = pack2bf_lo(h[4], h[5]); lv.w = pack2bf_lo(h[6], h[7]);
                        *(uint4*)(hhi + (size_t)grow * 128 + col) = hv;
                        *(uint4*)(hlo + (size_t)grow * 128 + col) = lv;
                        if (write_musd) {
                            float* p = sd_out + (size_t)grow * 128 + col;
                            *(float4*)(p + 0) = make_float4(s[0], s[1], s[2], s[3]);
                            *(float4*)(p + 4) = make_float4(s[4], s[5], s[6], s[7]);
                        }
                    }
                }
                __syncwarp();
            }
        }
        // next iteration's post-wait __syncthreads orders sA writes before MMA reads
    }
}

// ---------------- SIMT GEMM (tiny decoder layers) ----------------
template <int KI, int KO, int ACT, int ROWS>
__global__ __launch_bounds__(256) void gemm_kernel(
    const float* __restrict__ A, const float* __restrict__ W,
    const float* __restrict__ bias, float* __restrict__ C, int n)
{
    constexpr int BC = (KO < 32) ? KO : 32;
    constexpr int BR = 256 / BC;
    constexpr int RT = ROWS / BR;
    constexpr int CT = KO / BC;
    constexpr int KC = (KI < 32) ? KI : 32;

    __shared__ float As[ROWS][KC];
    __shared__ float Ws[KC][KO];
    const int tid = threadIdx.x;
    const int tx = tid % BC;
    const int ty = tid / BC;
    const int row0 = blockIdx.x * ROWS;

    float acc[RT][CT];
#pragma unroll
    for (int i = 0; i < RT; i++)
#pragma unroll
        for (int j = 0; j < CT; j++) acc[i][j] = 0.f;

    for (int k0 = 0; k0 < KI; k0 += KC) {
        if (k0) __syncthreads();
        for (int i = tid; i < KC * KO; i += 256)
            Ws[i / KO][i % KO] = W[(size_t)k0 * KO + i];
        for (int i = tid; i < ROWS * KC; i += 256) {
            int r = i / KC, kk = i % KC;
            int gr = row0 + r;
            As[r][kk] = (gr < n) ? A[(size_t)gr * KI + k0 + kk] : 0.f;
        }
        __syncthreads();
#pragma unroll
        for (int kk = 0; kk < KC; kk++) {
            float av[RT], wv[CT];
#pragma unroll
            for (int i = 0; i < RT; i++) av[i] = As[ty * RT + i][kk];
#pragma unroll
            for (int j = 0; j < CT; j++) wv[j] = Ws[kk][j * BC + tx];
#pragma unroll
            for (int i = 0; i < RT; i++)
#pragma unroll
                for (int j = 0; j < CT; j++) acc[i][j] += av[i] * wv[j];
        }
    }
#pragma unroll
    for (int j = 0; j < CT; j++) {
        int col = j * BC + tx;
        float bv = bias[col];
#pragma unroll
        for (int i = 0; i < RT; i++) {
            int r = row0 + ty * RT + i;
            if (r < n) C[(size_t)r * KO + col] = apply_act<ACT>(acc[i][j] + bv);
        }
    }
}

// ---------------- degree / dinv ----------------
__global__ void k_deg_init(float* dinv, int n) {
    int i = blockIdx.x * blockDim.x + threadIdx.x;
    if (i < n) dinv[i] = 1.f;
}
__global__ void k_deg_acc(const int* __restrict__ dst, float* dinv, int E) {
    int i = blockIdx.x * blockDim.x + threadIdx.x;
    if (i < E) atomicAdd(&dinv[dst[i]], 1.f);
}
__global__ void k_deg_fin(float* dinv, int n) {
    int i = blockIdx.x * blockDim.x + threadIdx.x;
    if (i < n) dinv[i] = rsqrtf(dinv[i]);
}

// ---------------- GCN edge scatter ----------------
__global__ void k_scatter_edges(const int* __restrict__ src, const int* __restrict__ dst,
                                const float* __restrict__ dinv, const float* __restrict__ g,
                                float* __restrict__ o, int E)
{
    int t = blockIdx.x * blockDim.x + threadIdx.x;
    int e = t >> 5;
    if (e >= E) return;
    int lane = t & 31;
    int s = 0, d = 0;
    float w = 0.f;
    if (lane == 0) {
        s = src[e];
        d = dst[e];
        w = dinv[s] * dinv[d];
    }
    s = __shfl_sync(0xffffffffu, s, 0);
    d = __shfl_sync(0xffffffffu, d, 0);
    w = __shfl_sync(0xffffffffu, w, 0);
    float4 v = *(const float4*)(g + (size_t)s * 128 + lane * 4);
    float* p = o + (size_t)d * 128 + lane * 4;
    asm volatile("red.global.add.v4.f32 [%0], {%1, %2, %3, %4};"
                 :: "l"(p), "f"(v.x * w), "f"(v.y * w), "f"(v.z * w), "f"(v.w * w)
                 : "memory");
}

// ---------------- final 16 -> 10 ----------------
__global__ void k_final10(const float* __restrict__ A, const float* __restrict__ Wo,
                          const float* __restrict__ bo, float* __restrict__ yp, int n)
{
    __shared__ float w[160];
    __shared__ float bb[10];
    if (threadIdx.x < 160) w[threadIdx.x] = Wo[threadIdx.x];
    if (threadIdx.x < 10) bb[threadIdx.x] = bo[threadIdx.x];
    __syncthreads();
    int i = blockIdx.x * blockDim.x + threadIdx.x;
    if (i >= n) return;
    float a[16];
#pragma unroll
    for (int k = 0; k < 16; k++) a[k] = A[(size_t)i * 16 + k];
#pragma unroll
    for (int c = 0; c < 10; c++) {
        float s = bb[c];
#pragma unroll
        for (int k = 0; k < 16; k++) s += a[k] * w[k * 10 + c];
        yp[(size_t)i * 10 + c] = 1.f / (1.f + expf(-s));
    }
}

// ---------------- pooling ----------------
__global__ void k_pool_init(float* sums, float* cnt, int gsz) {
    int i = blockIdx.x * blockDim.x + threadIdx.x;
    if (i < gsz * 10) sums[i] = 0.f;
    if (i < gsz) cnt[i] = 0.f;
}
__global__ void k_pool_acc(const float* __restrict__ yp, const int* __restrict__ bids,
                           float* sums, float* cnt, int n)
{
    int i = blockIdx.x * blockDim.x + threadIdx.x;
    if (i >= n) return;
    int b = bids[i];
    const float* r = yp + (size_t)i * 10;
#pragma unroll
    for (int c = 0; c < 10; c++) atomicAdd(&sums[b * 10 + c], r[c]);
    atomicAdd(&cnt[b], 1.f);
}
__global__ void k_pool_fin(const float* __restrict__ sums, const float* __restrict__ cnt,
                           const float* __restrict__ y, float* __restrict__ out,
                           float* __restrict__ yout, int tot)
{
    int i = blockIdx.x * blockDim.x + threadIdx.x;
    if (i >= tot) return;
    out[i] = sums[i] / fmaxf(cnt[i / 10], 1.f);
    yout[i] = y[i];
}

// ---------------- host helpers ----------------
template <int KI, int KO, int ACT, bool APL, bool OPL>
static void run2(const float* Af, const __nv_bfloat16* Ahi, const __nv_bfloat16* Alo, int lda,
                 const __nv_bfloat16* Whi, const __nv_bfloat16* Wlo, const float* bias,
                 float* Cf, __nv_bfloat16* Chi, __nv_bfloat16* Clo, int ldc, int n,
                 const float* dinv = nullptr, float* Cf2 = nullptr)
{
    constexpr int KC = (KI < 128) ? KI : 128;
    constexpr int SMB = (128 * (KC + 8) + KC * (KO + 8)) * 2 * 2;
    cudaFuncSetAttribute(wm2<KI, KO, ACT, APL, OPL>,
                         cudaFuncAttributeMaxDynamicSharedMemorySize, SMB);
    wm2<KI, KO, ACT, APL, OPL><<<(n + 127) / 128, 256, SMB>>>(
        Af, Ahi, Alo, lda, Whi, Wlo, bias, Cf, Chi, Clo, ldc, n, dinv, Cf2);
}

extern "C" void kernel_launch(void* const* d_in, const int* in_sizes, int n_in,
                              void* d_out, int out_size)
{
    const float* x     = (const float*)d_in[0];
    const int*   ei    = (const int*)d_in[1];
    const int*   bids  = (const int*)d_in[2];
    const float* y     = (const float*)d_in[3];
    const float* eps   = (const float*)d_in[4];
    const float* W_in  = (const float*)d_in[5];
    const float* b_in  = (const float*)d_in[6];
    const float* W_gcn = (const float*)d_in[7];
    const float* b_gcn = (const float*)d_in[8];
    const float* W_enc = (const float*)d_in[9];
    const float* b_enc = (const float*)d_in[10];
    const float* W_mu  = (const float*)d_in[11];
    const float* b_mu  = (const float*)d_in[12];
    const float* W_std = (const float*)d_in[13];
    const float* b_std = (const float*)d_in[14];
    const float* Wd0 = (const float*)d_in[15]; const float* bd0 = (const float*)d_in[16];
    const float* Wd1 = (const float*)d_in[17]; const float* bd1 = (const float*)d_in[18];
    const float* Wd2 = (const float*)d_in[19]; const float* bd2 = (const float*)d_in[20];
    const float* Wd3 = (const float*)d_in[21]; const float* bd3 = (const float*)d_in[22];
    const float* Wd4 = (const float*)d_in[23]; const float* bd4 = (const float*)d_in[24];
    const float* Wo  = (const float*)d_in[25]; const float* bo  = (const float*)d_in[26];

    const int N = in_sizes[2];
    const int E = in_sizes[1] / 2;
    const int G = in_sizes[3] / 10;
    const int* src = ei;
    const int* dst = ei + E;

    float *dinv, *a, *b, *yp, *sums, *cnt;
    __nv_bfloat16 *hhi, *hlo, *p0hi, *p0lo, *p1hi, *p1lo, *whi, *wlo;
    cudaGetSymbolAddress((void**)&dinv, g_dinv);
    cudaGetSymbolAddress((void**)&a,    g_a);
    cudaGetSymbolAddress((void**)&b,    g_b);
    cudaGetSymbolAddress((void**)&yp,   g_yp);
    cudaGetSymbolAddress((void**)&sums, g_sums);
    cudaGetSymbolAddress((void**)&cnt,  g_cnt);
    cudaGetSymbolAddress((void**)&hhi,  g_hhi);
    cudaGetSymbolAddress((void**)&hlo,  g_hlo);
    cudaGetSymbolAddress((void**)&p0hi, g_p0hi);
    cudaGetSymbolAddress((void**)&p0lo, g_p0lo);
    cudaGetSymbolAddress((void**)&p1hi, g_p1hi);
    cudaGetSymbolAddress((void**)&p1lo, g_p1lo);
    cudaGetSymbolAddress((void**)&whi,  g_whi);
    cudaGetSymbolAddress((void**)&wlo,  g_wlo);

    float* out    = (float*)d_out;
    float* mu_out = out + (size_t)G * 10;
    float* sd_out = mu_out + (size_t)N * 128;
    float* y_out  = sd_out + (size_t)N * 128;

    const int TB = 256;
    const int gb128 = (N + 127) / 128;

    // ---- weight split prep (single launch) ----
    {
        PrepSrc ps;
        ps.s[0] = W_in;  ps.s[1] = W_gcn; ps.s[2] = W_enc; ps.s[3] = W_mu;
        ps.s[4] = W_std; ps.s[5] = Wd0;   ps.s[6] = Wd1;   ps.s[7] = Wd2;
        k_prep_all<<<(WTOT + 255) / 256, 256>>>(ps, whi, wlo);
    }

    // ---- degrees ----
    k_deg_init<<<(N + TB - 1) / TB, TB>>>(dinv, N);
    k_deg_acc<<<(E + TB - 1) / TB, TB>>>(dst, dinv, E);
    k_deg_fin<<<(N + TB - 1) / TB, TB>>>(dinv, N);

    // ---- input layer ----
    run2<32, 128, 1, false, true>(x, nullptr, nullptr, 32,
                                  whi + WOFF_IN, wlo + WOFF_IN, b_in,
                                  nullptr, hhi, hlo, 128, N);

    cudaFuncSetAttribute(enc_fused, cudaFuncAttributeMaxDynamicSharedMemorySize, EF_SMEM);

    for (int hop = 0; hop < 3; hop++) {
        // gcn + fused scatter-init: a = raw g, b = g*dinv^2 + b_gcn
        run2<128, 128, 5, true, false>(nullptr, hhi, hlo, 128,
                                       whi + WOFF_GCN, wlo + WOFF_GCN, b_gcn,
                                       a, nullptr, nullptr, 128, N, dinv, b);
        k_scatter_edges<<<((size_t)E * 32 + TB - 1) / TB, TB>>>(src, dst, dinv, a, b, E);
        enc_fused<<<gb128, 256, EF_SMEM>>>(b, whi, wlo, b_enc, b_mu, b_std,
                                           eps + (size_t)hop * N * 128,
                                           hhi, hlo, mu_out, sd_out,
                                           (hop == 2) ? 1 : 0, N);
    }

    // ---- decoder ----
    run2<128, 128, 2, true, true>(nullptr, hhi, hlo, 128,
                                  whi + WOFF_D0, wlo + WOFF_D0, bd0,
                                  nullptr, p1hi, p1lo, 256, N);
    run2<128, 128, 2, true, true>(nullptr, hhi, hlo, 128,
                                  whi + WOFF_D0 + 128, wlo + WOFF_D0 + 128, bd0 + 128,
                                  nullptr, p1hi + 128, p1lo + 128, 256, N);
    run2<256, 128, 2, true, true>(nullptr, p1hi, p1lo, 256,
                                  whi + WOFF_D1, wlo + WOFF_D1, bd1,
                                  nullptr, p0hi, p0lo, 128, N);
    run2<128, 64, 2, true, false>(nullptr, p0hi, p0lo, 128,
                                  whi + WOFF_D2, wlo + WOFF_D2, bd2,
                                  b, nullptr, nullptr, 64, N);
    gemm_kernel<64, 32, 2, 128><<<gb128, TB>>>(b, Wd3, bd3, a, N);
    gemm_kernel<32, 16, 2, 128><<<gb128, TB>>>(a, Wd4, bd4, b, N);
    k_final10<<<(N + TB - 1) / TB, TB>>>(b, Wo, bo, yp, N);

    // ---- pooling ----
    k_pool_init<<<(G * 10 + TB - 1) / TB, TB>>>(sums, cnt, G);
    k_pool_acc<<<(N + TB - 1) / TB, TB>>>(yp, bids, sums, cnt, N);
    k_pool_fin<<<(G * 10 + TB - 1) / TB, TB>>>(sums, cnt, y, out, y_out, G * 10);
}

// round 7
// speedup vs baseline: 2.1060x; 1.1825x over previous
#include <cuda_runtime.h>
#include <cuda_bf16.h>
#include <mma.h>
#include <math.h>
#include <stdint.h>

using namespace nvcuda;

#define MAXN  50000
#define MAXE  800000
#define NPAD  50176

// ---------------- device scratch ----------------
__device__ float g_dinv[MAXN];
__device__ float g_a[(size_t)MAXN * 128];
__device__ float g_b[(size_t)MAXN * 256];
__device__ float g_yp[(size_t)MAXN * 10];
__device__ float g_sums[256 * 10];
__device__ float g_cntf[256];

// CSR
__device__ int   g_cnti[MAXN];
__device__ int   g_cur[MAXN];
__device__ int   g_excl[MAXN];
__device__ int   g_bsum[256];
__device__ int   g_boff[256];
__device__ int   g_eoff[MAXN + 1];
__device__ int   g_esrc[MAXE];
__device__ float g_ew[MAXE];

__device__ __nv_bfloat16 g_hhi[(size_t)NPAD * 128];
__device__ __nv_bfloat16 g_hlo[(size_t)NPAD * 128];
__device__ __nv_bfloat16 g_p0hi[(size_t)NPAD * 256];
__device__ __nv_bfloat16 g_p0lo[(size_t)NPAD * 256];
__device__ __nv_bfloat16 g_p1hi[(size_t)NPAD * 256];
__device__ __nv_bfloat16 g_p1lo[(size_t)NPAD * 256];

#define WOFF_IN  0
#define WOFF_GCN 4096
#define WOFF_ENC 20480
#define WOFF_MU  102400
#define WOFF_STD 118784
#define WOFF_D0  135168
#define WOFF_D1  167936
#define WOFF_D2  200704
#define WTOT     208896
__device__ __nv_bfloat16 g_whi[WTOT];
__device__ __nv_bfloat16 g_wlo[WTOT];

// ---------------- helpers ----------------
__device__ __forceinline__ uint32_t smem_u32(const void* p) {
    uint32_t a;
    asm("{ .reg .u64 t; cvta.to.shared.u64 t, %1; cvt.u32.u64 %0, t; }" : "=r"(a) : "l"(p));
    return a;
}
__device__ __forceinline__ void cpa16(uint32_t dst, const void* src) {
    asm volatile("cp.async.ca.shared.global [%0], [%1], 16;" :: "r"(dst), "l"(src));
}
#define CPA_COMMIT() asm volatile("cp.async.commit_group;" ::: "memory")
#define CPA_WAIT()   asm volatile("cp.async.wait_group 0;" ::: "memory")

// ACT: 0 lin+bias, 1 sigmoid, 2 relu, 3 softplus(v-5), 4 lin no-bias
template <int ACT>
__device__ __forceinline__ float apply_act(float v) {
    if (ACT == 1) return 1.f / (1.f + expf(-v));
    if (ACT == 2) return fmaxf(v, 0.f);
    if (ACT == 3) {
        float z = v - 5.f;
        return fmaxf(z, 0.f) + log1pf(expf(-fabsf(z)));
    }
    return v;
}

__device__ __forceinline__ uint32_t pack2bf(float a, float b) {
    __nv_bfloat16 ha = __float2bfloat16(a), hb = __float2bfloat16(b);
    return (uint32_t)__bfloat16_as_ushort(ha) | ((uint32_t)__bfloat16_as_ushort(hb) << 16);
}
__device__ __forceinline__ uint32_t pack2bf_lo(float a, float b) {
    __nv_bfloat16 ha = __float2bfloat16(a), hb = __float2bfloat16(b);
    float ra = a - __bfloat162float(ha), rb = b - __bfloat162float(hb);
    __nv_bfloat16 la = __float2bfloat16(ra), lb = __float2bfloat16(rb);
    return (uint32_t)__bfloat16_as_ushort(la) | ((uint32_t)__bfloat16_as_ushort(lb) << 16);
}

// ---------------- one-launch weight split prep ----------------
struct PrepSrc { const float* s[8]; };
__constant__ int c_woff[9] = {WOFF_IN, WOFF_GCN, WOFF_ENC, WOFF_MU, WOFF_STD,
                              WOFF_D0, WOFF_D1, WOFF_D2, WTOT};
__global__ void k_prep_all(PrepSrc ps, __nv_bfloat16* __restrict__ hi,
                           __nv_bfloat16* __restrict__ lo)
{
    int i = blockIdx.x * blockDim.x + threadIdx.x;
    if (i >= WTOT) return;
    int r = 0;
#pragma unroll
    for (int k = 1; k < 8; k++) if (i >= c_woff[k]) r = k;
    float v = ps.s[r][i - c_woff[r]];
    __nv_bfloat16 h = __float2bfloat16(v);
    hi[i] = h;
    lo[i] = __float2bfloat16(v - __bfloat162float(h));
}

// ---------------- CSR build ----------------
__global__ void k_zero2(int* a, int* b, int n) {
    int i = blockIdx.x * blockDim.x + threadIdx.x;
    if (i < n) { a[i] = 0; b[i] = 0; }
}
__global__ void k_indeg(const int* __restrict__ dst, int* cnt, int E) {
    int i = blockIdx.x * blockDim.x + threadIdx.x;
    if (i < E) atomicAdd(&cnt[dst[i]], 1);
}
__global__ void k_deg_fin(const int* __restrict__ cnt, float* dinv, int n) {
    int i = blockIdx.x * blockDim.x + threadIdx.x;
    if (i < n) dinv[i] = rsqrtf((float)cnt[i] + 1.f);
}
__global__ void k_scan1(const int* __restrict__ cnt, int* bsum, int* excl, int n) {
    __shared__ int sh[256];
    int t = threadIdx.x, i = blockIdx.x * 256 + t;
    int v = (i < n) ? cnt[i] : 0;
    sh[t] = v;
    __syncthreads();
    for (int o = 1; o < 256; o <<= 1) {
        int x = (t >= o) ? sh[t - o] : 0;
        __syncthreads();
        sh[t] += x;
        __syncthreads();
    }
    if (i < n) excl[i] = sh[t] - v;
    if (t == 255) bsum[blockIdx.x] = sh[255];
}
__global__ void k_scan2(const int* __restrict__ bsum, int* boff, int nb) {
    __shared__ int sh[256];
    int t = threadIdx.x;
    int v = (t < nb) ? bsum[t] : 0;
    sh[t] = v;
    __syncthreads();
    for (int o = 1; o < 256; o <<= 1) {
        int x = (t >= o) ? sh[t - o] : 0;
        __syncthreads();
        sh[t] += x;
        __syncthreads();
    }
    if (t < nb) boff[t] = sh[t] - v;
}
__global__ void k_scan3(const int* __restrict__ excl, const int* __restrict__ boff,
                        int* eoff, int n, int E) {
    int i = blockIdx.x * blockDim.x + threadIdx.x;
    if (i < n) eoff[i] = excl[i] + boff[i >> 8];
    if (i == 0) eoff[n] = E;
}
__global__ void k_fill(const int* __restrict__ src, const int* __restrict__ dst,
                       const float* __restrict__ dinv, const int* __restrict__ eoff,
                       int* cur, int* esrc, float* ew, int E) {
    int i = blockIdx.x * blockDim.x + threadIdx.x;
    if (i >= E) return;
    int d = dst[i], s = src[i];
    int pos = eoff[d] + atomicAdd(&cur[d], 1);
    esrc[pos] = s;
    ew[pos] = dinv[s] * dinv[d];
}

// ---------------- gather-reduce: o = g[dst]*dinv^2 + b_gcn + sum w*g[src] ----------------
__global__ __launch_bounds__(256) void k_gather(
    const float* __restrict__ a, const int* __restrict__ eoff,
    const int* __restrict__ esrc, const float* __restrict__ ew,
    const float* __restrict__ dinv, const float* __restrict__ bias,
    __nv_bfloat16* __restrict__ ohi, __nv_bfloat16* __restrict__ olo, int n)
{
    int node = blockIdx.x * 8 + (threadIdx.x >> 5);
    if (node >= n) return;
    int lane = threadIdx.x & 31;
    int c4 = lane * 4;
    float dv = dinv[node];
    float sc = dv * dv;
    float4 v = *(const float4*)(a + (size_t)node * 128 + c4);
    float a0 = v.x * sc + bias[c4 + 0];
    float a1 = v.y * sc + bias[c4 + 1];
    float a2 = v.z * sc + bias[c4 + 2];
    float a3 = v.w * sc + bias[c4 + 3];
    int e0 = eoff[node], e1 = eoff[node + 1];
#pragma unroll 4
    for (int i = e0; i < e1; i++) {
        int s = esrc[i];
        float w = ew[i];
        float4 u = *(const float4*)(a + (size_t)s * 128 + c4);
        a0 += w * u.x; a1 += w * u.y; a2 += w * u.z; a3 += w * u.w;
    }
    uint2 hv, lv;
    hv.x = pack2bf(a0, a1);    hv.y = pack2bf(a2, a3);
    lv.x = pack2bf_lo(a0, a1); lv.y = pack2bf_lo(a2, a3);
    *(uint2*)(ohi + (size_t)node * 128 + c4) = hv;
    *(uint2*)(olo + (size_t)node * 128 + c4) = lv;
}

// ---------------- WMMA GEMM on bf16 hi/lo planes ----------------
template <int KI, int KO, int ACT, bool APL, bool OPL>
__global__ __launch_bounds__(256) void wm2(
    const float* __restrict__ Af,
    const __nv_bfloat16* __restrict__ Ahi, const __nv_bfloat16* __restrict__ Alo, int lda,
    const __nv_bfloat16* __restrict__ Whi, const __nv_bfloat16* __restrict__ Wlo,
    const float* __restrict__ bias,
    float* __restrict__ Cf, __nv_bfloat16* __restrict__ Chi, __nv_bfloat16* __restrict__ Clo,
    int ldc, int n)
{
    constexpr int KC  = (KI < 128) ? KI : 128;
    constexpr int NCH = KI / KC;
    constexpr int LDA = KC + 8;
    constexpr int LDW = KO + 8;
    constexpr int NJT = KO / 32;
    constexpr int AE  = 128 * LDA;
    constexpr int WE  = KC * LDW;

    extern __shared__ char smraw[];
    __nv_bfloat16* sAhi = (__nv_bfloat16*)smraw;
    __nv_bfloat16* sAlo = sAhi + AE;
    __nv_bfloat16* sWhi = sAlo + AE;
    __nv_bfloat16* sWlo = sWhi + WE;

    const int tid  = threadIdx.x;
    const int wid  = tid >> 5;
    const int lane = tid & 31;
    const int rg   = wid >> 1;
    const int cg   = wid & 1;
    const int row0 = blockIdx.x * 128;

    wmma::fragment<wmma::accumulator, 16, 16, 16, float> acc[2][NJT];
#pragma unroll
    for (int i = 0; i < 2; i++)
#pragma unroll
        for (int j = 0; j < NJT; j++) wmma::fill_fragment(acc[i][j], 0.f);

    const uint32_t sAhiB = smem_u32(sAhi);
    const uint32_t sAloB = smem_u32(sAlo);
    const uint32_t sWhiB = smem_u32(sWhi);
    const uint32_t sWloB = smem_u32(sWlo);

    for (int ch = 0; ch < NCH; ch++) {
        if (ch) __syncthreads();
        if (APL) {
            constexpr int U = KC / 8;
            for (int i = tid; i < 128 * U; i += 256) {
                int r = i / U, u = i % U;
                size_t g = (size_t)(row0 + r) * lda + ch * KC + u * 8;
                uint32_t d = (uint32_t)(r * LDA + u * 8) * 2;
                cpa16(sAhiB + d, Ahi + g);
                cpa16(sAloB + d, Alo + g);
            }
        } else {
            constexpr int Q = KC / 4;
            for (int i = tid; i < 128 * Q; i += 256) {
                int r = i / Q, q = i % Q;
                float4 v = make_float4(0.f, 0.f, 0.f, 0.f);
                if (row0 + r < n)
                    v = *(const float4*)(Af + (size_t)(row0 + r) * lda + ch * KC + 4 * q);
                uint2 hv, lv;
                hv.x = pack2bf(v.x, v.y);    hv.y = pack2bf(v.z, v.w);
                lv.x = pack2bf_lo(v.x, v.y); lv.y = pack2bf_lo(v.z, v.w);
                *(uint2*)(sAhi + r * LDA + 4 * q) = hv;
                *(uint2*)(sAlo + r * LDA + 4 * q) = lv;
            }
        }
        {
            constexpr int U = KO / 8;
            for (int i = tid; i < KC * U; i += 256) {
                int r = i / U, u = i % U;
                size_t g = (size_t)(ch * KC + r) * KO + u * 8;
                uint32_t d = (uint32_t)(r * LDW + u * 8) * 2;
                cpa16(sWhiB + d, Whi + g);
                cpa16(sWloB + d, Wlo + g);
            }
        }
        CPA_COMMIT();
        CPA_WAIT();
        __syncthreads();

#pragma unroll
        for (int k = 0; k < KC / 16; k++) {
            wmma::fragment<wmma::matrix_a, 16, 16, 16, __nv_bfloat16, wmma::row_major> ah[2], al[2];
#pragma unroll
            for (int i = 0; i < 2; i++) {
                int r = rg * 32 + i * 16;
                wmma::load_matrix_sync(ah[i], sAhi + r * LDA + k * 16, LDA);
                wmma::load_matrix_sync(al[i], sAlo + r * LDA + k * 16, LDA);
            }
#pragma unroll
            for (int j = 0; j < NJT; j++) {
                int c = cg * (KO / 2) + j * 16;
                wmma::fragment<wmma::matrix_b, 16, 16, 16, __nv_bfloat16, wmma::row_major> bh, bl;
                wmma::load_matrix_sync(bh, sWhi + k * 16 * LDW + c, LDW);
                wmma::load_matrix_sync(bl, sWlo + k * 16 * LDW + c, LDW);
#pragma unroll
                for (int i = 0; i < 2; i++) {
                    wmma::mma_sync(acc[i][j], ah[i], bh, acc[i][j]);
                    wmma::mma_sync(acc[i][j], ah[i], bl, acc[i][j]);
                    wmma::mma_sync(acc[i][j], al[i], bh, acc[i][j]);
                }
            }
        }
    }
    __syncthreads();

    float* stage = (float*)smraw + wid * 320;
    const int r8 = lane >> 1;
    const int c8 = (lane & 1) * 8;
#pragma unroll
    for (int i = 0; i < 2; i++) {
        const int grow = row0 + rg * 32 + i * 16 + r8;
#pragma unroll
        for (int j = 0; j < NJT; j++) {
            wmma::store_matrix_sync(stage, acc[i][j], 20, wmma::mem_row_major);
            __syncwarp();
            if (grow < n) {
                const int col = cg * (KO / 2) + j * 16 + c8;
                float o[8];
#pragma unroll
                for (int q = 0; q < 8; q++) {
                    float v = stage[r8 * 20 + c8 + q];
                    if (ACT != 4) v += bias[col + q];
                    o[q] = apply_act<ACT>(v);
                }
                if (OPL) {
                    uint4 hv, lv;
                    hv.x = pack2bf(o[0], o[1]); hv.y = pack2bf(o[2], o[3]);
                    hv.z = pack2bf(o[4], o[5]); hv.w = pack2bf(o[6], o[7]);
                    lv.x = pack2bf_lo(o[0], o[1]); lv.y = pack2bf_lo(o[2], o[3]);
                    lv.z = pack2bf_lo(o[4], o[5]); lv.w = pack2bf_lo(o[6], o[7]);
                    *(uint4*)(Chi + (size_t)grow * ldc + col) = hv;
                    *(uint4*)(Clo + (size_t)grow * ldc + col) = lv;
                } else {
                    float* p = Cf + (size_t)grow * ldc + col;
                    *(float4*)(p + 0) = make_float4(o[0], o[1], o[2], o[3]);
                    *(float4*)(p + 4) = make_float4(o[4], o[5], o[6], o[7]);
                }
            }
            __syncwarp();
        }
    }
}

// ---------------- fused encoder block: enc0..4 + mu + std + reparam ----------------
#define EF_LDA 136
#define EF_AE  (128 * EF_LDA)
#define EF_SMEM (4 * EF_AE * 2 + 128 * 132 * 4 + 8 * 320 * 4)

__global__ __launch_bounds__(256) void enc_fused(
    const __nv_bfloat16* __restrict__ Bhi, const __nv_bfloat16* __restrict__ Blo,
    const __nv_bfloat16* __restrict__ whi, const __nv_bfloat16* __restrict__ wlo,
    const float* __restrict__ b_enc, const float* __restrict__ b_mu,
    const float* __restrict__ b_std, const float* __restrict__ eps,
    __nv_bfloat16* __restrict__ hhi, __nv_bfloat16* __restrict__ hlo,
    float* __restrict__ mu_out, float* __restrict__ sd_out, int write_musd, int n)
{
    extern __shared__ char smraw[];
    __nv_bfloat16* sAhi = (__nv_bfloat16*)smraw;
    __nv_bfloat16* sAlo = sAhi + EF_AE;
    __nv_bfloat16* sWhi = sAlo + EF_AE;
    __nv_bfloat16* sWlo = sWhi + EF_AE;
    float* sMu   = (float*)(sWlo + EF_AE);
    float* stageB = sMu + 128 * 132;

    const int tid  = threadIdx.x;
    const int wid  = tid >> 5;
    const int lane = tid & 31;
    const int rg   = wid >> 1;
    const int cg   = wid & 1;
    const int row0 = blockIdx.x * 128;
    const int r8   = lane >> 1;
    const int c8   = (lane & 1) * 8;
    float* stage = stageB + wid * 320;

    const uint32_t sAhiB = smem_u32(sAhi);
    const uint32_t sAloB = smem_u32(sAlo);
    const uint32_t sWhiB = smem_u32(sWhi);
    const uint32_t sWloB = smem_u32(sWlo);

    // ---- input planes -> sA via cp.async ----
    for (int i = tid; i < 128 * 16; i += 256) {
        int r = i >> 4, u = i & 15;
        size_t g = (size_t)(row0 + r) * 128 + u * 8;
        uint32_t d = (uint32_t)(r * EF_LDA + u * 8) * 2;
        cpa16(sAhiB + d, Bhi + g);
        cpa16(sAloB + d, Blo + g);
    }

    for (int l = 0; l < 7; l++) {
        int woff = (l < 5) ? (WOFF_ENC + l * 16384) : ((l == 5) ? WOFF_MU : WOFF_STD);
        const __nv_bfloat16* Wh = whi + woff;
        const __nv_bfloat16* Wl = wlo + woff;
        for (int i = tid; i < 128 * 16; i += 256) {
            int r = i >> 4, u = i & 15;
            uint32_t d = (uint32_t)(r * EF_LDA + u * 8) * 2;
            cpa16(sWhiB + d, Wh + r * 128 + u * 8);
            cpa16(sWloB + d, Wl + r * 128 + u * 8);
        }
        CPA_COMMIT();
        CPA_WAIT();
        __syncthreads();

        wmma::fragment<wmma::accumulator, 16, 16, 16, float> acc[2][4];
#pragma unroll
        for (int i = 0; i < 2; i++)
#pragma unroll
            for (int j = 0; j < 4; j++) wmma::fill_fragment(acc[i][j], 0.f);
#pragma unroll
        for (int k = 0; k < 8; k++) {
            wmma::fragment<wmma::matrix_a, 16, 16, 16, __nv_bfloat16, wmma::row_major> ah[2], al[2];
#pragma unroll
            for (int i = 0; i < 2; i++) {
                int r = rg * 32 + i * 16;
                wmma::load_matrix_sync(ah[i], sAhi + r * EF_LDA + k * 16, EF_LDA);
                wmma::load_matrix_sync(al[i], sAlo + r * EF_LDA + k * 16, EF_LDA);
            }
#pragma unroll
            for (int j = 0; j < 4; j++) {
                int c = cg * 64 + j * 16;
                wmma::fragment<wmma::matrix_b, 16, 16, 16, __nv_bfloat16, wmma::row_major> bh, bl;
                wmma::load_matrix_sync(bh, sWhi + k * 16 * EF_LDA + c, EF_LDA);
                wmma::load_matrix_sync(bl, sWlo + k * 16 * EF_LDA + c, EF_LDA);
#pragma unroll
                for (int i = 0; i < 2; i++) {
                    wmma::mma_sync(acc[i][j], ah[i], bh, acc[i][j]);
                    wmma::mma_sync(acc[i][j], ah[i], bl, acc[i][j]);
                    wmma::mma_sync(acc[i][j], al[i], bh, acc[i][j]);
                }
            }
        }
        __syncthreads();

#pragma unroll
        for (int i = 0; i < 2; i++) {
            const int lrow = rg * 32 + i * 16 + r8;
            const int grow = row0 + lrow;
#pragma unroll
            for (int j = 0; j < 4; j++) {
                wmma::store_matrix_sync(stage, acc[i][j], 20, wmma::mem_row_major);
                __syncwarp();
                const int col = cg * 64 + j * 16 + c8;
                if (l < 5) {
                    float o[8];
#pragma unroll
                    for (int q = 0; q < 8; q++) {
                        float v = stage[r8 * 20 + c8 + q] + b_enc[l * 128 + col + q];
                        o[q] = 1.f / (1.f + expf(-v));
                    }
                    uint4 hv, lv;
                    hv.x = pack2bf(o[0], o[1]); hv.y = pack2bf(o[2], o[3]);
                    hv.z = pack2bf(o[4], o[5]); hv.w = pack2bf(o[6], o[7]);
                    lv.x = pack2bf_lo(o[0], o[1]); lv.y = pack2bf_lo(o[2], o[3]);
                    lv.z = pack2bf_lo(o[4], o[5]); lv.w = pack2bf_lo(o[6], o[7]);
                    *(uint4*)(sAhi + lrow * EF_LDA + col) = hv;
                    *(uint4*)(sAlo + lrow * EF_LDA + col) = lv;
                } else if (l == 5) {
                    float o[8];
#pragma unroll
                    for (int q = 0; q < 8; q++) {
                        o[q] = stage[r8 * 20 + c8 + q] + b_mu[col + q];
                        sMu[lrow * 132 + col + q] = o[q];
                    }
                    if (write_musd && grow < n) {
                        float* p = mu_out + (size_t)grow * 128 + col;
                        *(float4*)(p + 0) = make_float4(o[0], o[1], o[2], o[3]);
                        *(float4*)(p + 4) = make_float4(o[4], o[5], o[6], o[7]);
                    }
                } else {
                    float s[8], h[8];
                    float4 e0 = make_float4(0.f, 0.f, 0.f, 0.f), e1 = e0;
                    if (grow < n) {
                        e0 = *(const float4*)(eps + (size_t)grow * 128 + col);
                        e1 = *(const float4*)(eps + (size_t)grow * 128 + col + 4);
                    }
                    float ev[8] = {e0.x, e0.y, e0.z, e0.w, e1.x, e1.y, e1.z, e1.w};
#pragma unroll
                    for (int q = 0; q < 8; q++) {
                        float z = stage[r8 * 20 + c8 + q] + b_std[col + q] - 5.f;
                        s[q] = fmaxf(z, 0.f) + log1pf(expf(-fabsf(z)));
                        h[q] = sMu[lrow * 132 + col + q] + s[q] * ev[q];
                    }
                    if (grow < n) {
                        uint4 hv, lv;
                        hv.x = pack2bf(h[0], h[1]); hv.y = pack2bf(h[2], h[3]);
                        hv.z = pack2bf(h[4], h[5]); hv.w = pack2bf(h[6], h[7]);
                        lv.x = pack2bf_lo(h[0], h[1]); lv.y = pack2bf_lo(h[2], h[3]);
                        lv.z = pack2bf_lo(h[4], h[5]); lv.w = pack2bf_lo(h[6], h[7]);
                        *(uint4*)(hhi + (size_t)grow * 128 + col) = hv;
                        *(uint4*)(hlo + (size_t)grow * 128 + col) = lv;
                        if (write_musd) {
                            float* p = sd_out + (size_t)grow * 128 + col;
                            *(float4*)(p + 0) = make_float4(s[0], s[1], s[2], s[3]);
                            *(float4*)(p + 4) = make_float4(s[4], s[5], s[6], s[7]);
                        }
                    }
                }
                __syncwarp();
            }
        }
    }
}

// ---------------- SIMT GEMM (tiny decoder layers) ----------------
template <int KI, int KO, int ACT, int ROWS>
__global__ __launch_bounds__(256) void gemm_kernel(
    const float* __restrict__ A, const float* __restrict__ W,
    const float* __restrict__ bias, float* __restrict__ C, int n)
{
    constexpr int BC = (KO < 32) ? KO : 32;
    constexpr int BR = 256 / BC;
    constexpr int RT = ROWS / BR;
    constexpr int CT = KO / BC;
    constexpr int KC = (KI < 32) ? KI : 32;

    __shared__ float As[ROWS][KC];
    __shared__ float Ws[KC][KO];
    const int tid = threadIdx.x;
    const int tx = tid % BC;
    const int ty = tid / BC;
    const int row0 = blockIdx.x * ROWS;

    float acc[RT][CT];
#pragma unroll
    for (int i = 0; i < RT; i++)
#pragma unroll
        for (int j = 0; j < CT; j++) acc[i][j] = 0.f;

    for (int k0 = 0; k0 < KI; k0 += KC) {
        if (k0) __syncthreads();
        for (int i = tid; i < KC * KO; i += 256)
            Ws[i / KO][i % KO] = W[(size_t)k0 * KO + i];
        for (int i = tid; i < ROWS * KC; i += 256) {
            int r = i / KC, kk = i % KC;
            int gr = row0 + r;
            As[r][kk] = (gr < n) ? A[(size_t)gr * KI + k0 + kk] : 0.f;
        }
        __syncthreads();
#pragma unroll
        for (int kk = 0; kk < KC; kk++) {
            float av[RT], wv[CT];
#pragma unroll
            for (int i = 0; i < RT; i++) av[i] = As[ty * RT + i][kk];
#pragma unroll
            for (int j = 0; j < CT; j++) wv[j] = Ws[kk][j * BC + tx];
#pragma unroll
            for (int i = 0; i < RT; i++)
#pragma unroll
                for (int j = 0; j < CT; j++) acc[i][j] += av[i] * wv[j];
        }
    }
#pragma unroll
    for (int j = 0; j < CT; j++) {
        int col = j * BC + tx;
        float bv = bias[col];
#pragma unroll
        for (int i = 0; i < RT; i++) {
            int r = row0 + ty * RT + i;
            if (r < n) C[(size_t)r * KO + col] = apply_act<ACT>(acc[i][j] + bv);
        }
    }
}

// ---------------- final 16 -> 10 ----------------
__global__ void k_final10(const float* __restrict__ A, const float* __restrict__ Wo,
                          const float* __restrict__ bo, float* __restrict__ yp, int n)
{
    __shared__ float w[160];
    __shared__ float bb[10];
    if (threadIdx.x < 160) w[threadIdx.x] = Wo[threadIdx.x];
    if (threadIdx.x < 10) bb[threadIdx.x] = bo[threadIdx.x];
    __syncthreads();
    int i = blockIdx.x * blockDim.x + threadIdx.x;
    if (i >= n) return;
    float a[16];
#pragma unroll
    for (int k = 0; k < 16; k++) a[k] = A[(size_t)i * 16 + k];
#pragma unroll
    for (int c = 0; c < 10; c++) {
        float s = bb[c];
#pragma unroll
        for (int k = 0; k < 16; k++) s += a[k] * w[k * 10 + c];
        yp[(size_t)i * 10 + c] = 1.f / (1.f + expf(-s));
    }
}

// ---------------- pooling ----------------
__global__ void k_pool_init(float* sums, float* cnt, int gsz) {
    int i = blockIdx.x * blockDim.x + threadIdx.x;
    if (i < gsz * 10) sums[i] = 0.f;
    if (i < gsz) cnt[i] = 0.f;
}
__global__ void k_pool_acc(const float* __restrict__ yp, const int* __restrict__ bids,
                           float* sums, float* cnt, int n)
{
    int i = blockIdx.x * blockDim.x + threadIdx.x;
    if (i >= n) return;
    int b = bids[i];
    const float* r = yp + (size_t)i * 10;
#pragma unroll
    for (int c = 0; c < 10; c++) atomicAdd(&sums[b * 10 + c], r[c]);
    atomicAdd(&cnt[b], 1.f);
}
__global__ void k_pool_fin(const float* __restrict__ sums, const float* __restrict__ cnt,
                           const float* __restrict__ y, float* __restrict__ out,
                           float* __restrict__ yout, int tot)
{
    int i = blockIdx.x * blockDim.x + threadIdx.x;
    if (i >= tot) return;
    out[i] = sums[i] / fmaxf(cnt[i / 10], 1.f);
    yout[i] = y[i];
}

// ---------------- host helpers ----------------
template <int KI, int KO, int ACT, bool APL, bool OPL>
static void run2(const float* Af, const __nv_bfloat16* Ahi, const __nv_bfloat16* Alo, int lda,
                 const __nv_bfloat16* Whi, const __nv_bfloat16* Wlo, const float* bias,
                 float* Cf, __nv_bfloat16* Chi, __nv_bfloat16* Clo, int ldc, int n)
{
    constexpr int KC = (KI < 128) ? KI : 128;
    constexpr int SMB = (128 * (KC + 8) + KC * (KO + 8)) * 2 * 2;
    cudaFuncSetAttribute(wm2<KI, KO, ACT, APL, OPL>,
                         cudaFuncAttributeMaxDynamicSharedMemorySize, SMB);
    wm2<KI, KO, ACT, APL, OPL><<<(n + 127) / 128, 256, SMB>>>(
        Af, Ahi, Alo, lda, Whi, Wlo, bias, Cf, Chi, Clo, ldc, n);
}

extern "C" void kernel_launch(void* const* d_in, const int* in_sizes, int n_in,
                              void* d_out, int out_size)
{
    const float* x     = (const float*)d_in[0];
    const int*   ei    = (const int*)d_in[1];
    const int*   bids  = (const int*)d_in[2];
    const float* y     = (const float*)d_in[3];
    const float* eps   = (const float*)d_in[4];
    const float* W_in  = (const float*)d_in[5];
    const float* b_in  = (const float*)d_in[6];
    const float* W_gcn = (const float*)d_in[7];
    const float* b_gcn = (const float*)d_in[8];
    const float* W_enc = (const float*)d_in[9];
    const float* b_enc = (const float*)d_in[10];
    const float* W_mu  = (const float*)d_in[11];
    const float* b_mu  = (const float*)d_in[12];
    const float* W_std = (const float*)d_in[13];
    const float* b_std = (const float*)d_in[14];
    const float* Wd0 = (const float*)d_in[15]; const float* bd0 = (const float*)d_in[16];
    const float* Wd1 = (const float*)d_in[17]; const float* bd1 = (const float*)d_in[18];
    const float* Wd2 = (const float*)d_in[19]; const float* bd2 = (const float*)d_in[20];
    const float* Wd3 = (const float*)d_in[21]; const float* bd3 = (const float*)d_in[22];
    const float* Wd4 = (const float*)d_in[23]; const float* bd4 = (const float*)d_in[24];
    const float* Wo  = (const float*)d_in[25]; const float* bo  = (const float*)d_in[26];

    const int N = in_sizes[2];
    const int E = in_sizes[1] / 2;
    const int G = in_sizes[3] / 10;
    const int* src = ei;
    const int* dst = ei + E;

    float *dinv, *a, *b, *yp, *sums, *cntf, *ew;
    int *cnti, *cur, *excl, *bsum, *boff, *eoff, *esrc;
    __nv_bfloat16 *hhi, *hlo, *p0hi, *p0lo, *p1hi, *p1lo, *whi, *wlo;
    cudaGetSymbolAddress((void**)&dinv, g_dinv);
    cudaGetSymbolAddress((void**)&a,    g_a);
    cudaGetSymbolAddress((void**)&b,    g_b);
    cudaGetSymbolAddress((void**)&yp,   g_yp);
    cudaGetSymbolAddress((void**)&sums, g_sums);
    cudaGetSymbolAddress((void**)&cntf, g_cntf);
    cudaGetSymbolAddress((void**)&cnti, g_cnti);
    cudaGetSymbolAddress((void**)&cur,  g_cur);
    cudaGetSymbolAddress((void**)&excl, g_excl);
    cudaGetSymbolAddress((void**)&bsum, g_bsum);
    cudaGetSymbolAddress((void**)&boff, g_boff);
    cudaGetSymbolAddress((void**)&eoff, g_eoff);
    cudaGetSymbolAddress((void**)&esrc, g_esrc);
    cudaGetSymbolAddress((void**)&ew,   g_ew);
    cudaGetSymbolAddress((void**)&hhi,  g_hhi);
    cudaGetSymbolAddress((void**)&hlo,  g_hlo);
    cudaGetSymbolAddress((void**)&p0hi, g_p0hi);
    cudaGetSymbolAddress((void**)&p0lo, g_p0lo);
    cudaGetSymbolAddress((void**)&p1hi, g_p1hi);
    cudaGetSymbolAddress((void**)&p1lo, g_p1lo);
    cudaGetSymbolAddress((void**)&whi,  g_whi);
    cudaGetSymbolAddress((void**)&wlo,  g_wlo);

    float* out    = (float*)d_out;
    float* mu_out = out + (size_t)G * 10;
    float* sd_out = mu_out + (size_t)N * 128;
    float* y_out  = sd_out + (size_t)N * 128;

    const int TB = 256;
    const int gb128 = (N + 127) / 128;
    const int nb = (N + 255) / 256;

    // ---- weight split prep ----
    {
        PrepSrc ps;
        ps.s[0] = W_in;  ps.s[1] = W_gcn; ps.s[2] = W_enc; ps.s[3] = W_mu;
        ps.s[4] = W_std; ps.s[5] = Wd0;   ps.s[6] = Wd1;   ps.s[7] = Wd2;
        k_prep_all<<<(WTOT + 255) / 256, 256>>>(ps, whi, wlo);
    }

    // ---- CSR build + degrees ----
    k_zero2<<<nb, TB>>>(cnti, cur, N);
    k_indeg<<<(E + TB - 1) / TB, TB>>>(dst, cnti, E);
    k_deg_fin<<<nb, TB>>>(cnti, dinv, N);
    k_scan1<<<nb, 256>>>(cnti, bsum, excl, N);
    k_scan2<<<1, 256>>>(bsum, boff, nb);
    k_scan3<<<nb, 256>>>(excl, boff, eoff, N, E);
    k_fill<<<(E + TB - 1) / TB, TB>>>(src, dst, dinv, eoff, cur, esrc, ew, E);

    // ---- input layer ----
    run2<32, 128, 1, false, true>(x, nullptr, nullptr, 32,
                                  whi + WOFF_IN, wlo + WOFF_IN, b_in,
                                  nullptr, hhi, hlo, 128, N);

    cudaFuncSetAttribute(enc_fused, cudaFuncAttributeMaxDynamicSharedMemorySize, EF_SMEM);

    for (int hop = 0; hop < 3; hop++) {
        // gcn: h planes -> raw g (fp32 a), no bias
        run2<128, 128, 4, true, false>(nullptr, hhi, hlo, 128,
                                       whi + WOFF_GCN, wlo + WOFF_GCN, nullptr,
                                       a, nullptr, nullptr, 128, N);
        // gather-reduce -> p0 planes
        k_gather<<<(N + 7) / 8, 256>>>(a, eoff, esrc, ew, dinv, b_gcn, p0hi, p0lo, N);
        enc_fused<<<gb128, 256, EF_SMEM>>>(p0hi, p0lo, whi, wlo, b_enc, b_mu, b_std,
                                           eps + (size_t)hop * N * 128,
                                           hhi, hlo, mu_out, sd_out,
                                           (hop == 2) ? 1 : 0, N);
    }

    // ---- decoder ----
    run2<128, 128, 2, true, true>(nullptr, hhi, hlo, 128,
                                  whi + WOFF_D0, wlo + WOFF_D0, bd0,
                                  nullptr, p1hi, p1lo, 256, N);
    run2<128, 128, 2, true, true>(nullptr, hhi, hlo, 128,
                                  whi + WOFF_D0 + 128, wlo + WOFF_D0 + 128, bd0 + 128,
                                  nullptr, p1hi + 128, p1lo + 128, 256, N);
    run2<256, 128, 2, true, true>(nullptr, p1hi, p1lo, 256,
                                  whi + WOFF_D1, wlo + WOFF_D1, bd1,
                                  nullptr, p0hi, p0lo, 128, N);
    run2<128, 64, 2, true, false>(nullptr, p0hi, p0lo, 128,
                                  whi + WOFF_D2, wlo + WOFF_D2, bd2,
                                  b, nullptr, nullptr, 64, N);
    gemm_kernel<64, 32, 2, 128><<<gb128, TB>>>(b, Wd3, bd3, a, N);
    gemm_kernel<32, 16, 2, 128><<<gb128, TB>>>(a, Wd4, bd4, b, N);
    k_final10<<<(N + TB - 1) / TB, TB>>>(b, Wo, bo, yp, N);

    // ---- pooling ----
    k_pool_init<<<(G * 10 + TB - 1) / TB, TB>>>(sums, cntf, G);
    k_pool_acc<<<(N + TB - 1) / TB, TB>>>(yp, bids, sums, cntf, N);
    k_pool_fin<<<(G * 10 + TB - 1) / TB, TB>>>(sums, cntf, y, out, y_out, G * 10);
}

// round 9
// speedup vs baseline: 2.1500x; 1.0209x over previous
#include <cuda_runtime.h>
#include <cuda_bf16.h>
#include <mma.h>
#include <math.h>
#include <stdint.h>

using namespace nvcuda;

#define MAXN  50000
#define MAXE  800000
#define NPAD  50176

// ---------------- device scratch ----------------
__device__ float g_dinv[MAXN];
__device__ float g_a[(size_t)MAXN * 128];
__device__ float g_b[(size_t)MAXN * 256];
__device__ float g_sums[256 * 10];
__device__ float g_cntf[256];

// CSR
__device__ int   g_cnti[MAXN];
__device__ int   g_cur[MAXN];
__device__ int   g_excl[MAXN];
__device__ int   g_bsum[256];
__device__ int   g_boff[256];
__device__ int   g_eoff[MAXN + 1];
__device__ int   g_esrc[MAXE];
__device__ float g_ew[MAXE];

__device__ __nv_bfloat16 g_hhi[(size_t)NPAD * 128];
__device__ __nv_bfloat16 g_hlo[(size_t)NPAD * 128];
__device__ __nv_bfloat16 g_p0hi[(size_t)NPAD * 256];
__device__ __nv_bfloat16 g_p0lo[(size_t)NPAD * 256];
__device__ __nv_bfloat16 g_p1hi[(size_t)NPAD * 256];
__device__ __nv_bfloat16 g_p1lo[(size_t)NPAD * 256];

#define WOFF_IN  0
#define WOFF_GCN 4096
#define WOFF_ENC 20480
#define WOFF_MU  102400
#define WOFF_STD 118784
#define WOFF_D0  135168
#define WOFF_D1  167936
#define WOFF_D2  200704
#define WTOT     208896
__device__ __nv_bfloat16 g_whi[WTOT];
__device__ __nv_bfloat16 g_wlo[WTOT];

// ---------------- helpers ----------------
__device__ __forceinline__ uint32_t smem_u32(const void* p) {
    uint32_t a;
    asm("{ .reg .u64 t; cvta.to.shared.u64 t, %1; cvt.u32.u64 %0, t; }" : "=r"(a) : "l"(p));
    return a;
}
__device__ __forceinline__ void cpa16(uint32_t dst, const void* src) {
    asm volatile("cp.async.ca.shared.global [%0], [%1], 16;" :: "r"(dst), "l"(src));
}
#define CPA_COMMIT() asm volatile("cp.async.commit_group;" ::: "memory")
#define CPA_WAIT()   asm volatile("cp.async.wait_group 0;" ::: "memory")

// ACT: 0 lin+bias, 1 sigmoid, 2 relu, 3 softplus(v-5), 4 lin no-bias
template <int ACT>
__device__ __forceinline__ float apply_act(float v) {
    if (ACT == 1) return 1.f / (1.f + expf(-v));
    if (ACT == 2) return fmaxf(v, 0.f);
    if (ACT == 3) {
        float z = v - 5.f;
        return fmaxf(z, 0.f) + log1pf(expf(-fabsf(z)));
    }
    return v;
}

__device__ __forceinline__ uint32_t pack2bf(float a, float b) {
    __nv_bfloat16 ha = __float2bfloat16(a), hb = __float2bfloat16(b);
    return (uint32_t)__bfloat16_as_ushort(ha) | ((uint32_t)__bfloat16_as_ushort(hb) << 16);
}
__device__ __forceinline__ uint32_t pack2bf_lo(float a, float b) {
    __nv_bfloat16 ha = __float2bfloat16(a), hb = __float2bfloat16(b);
    float ra = a - __bfloat162float(ha), rb = b - __bfloat162float(hb);
    __nv_bfloat16 la = __float2bfloat16(ra), lb = __float2bfloat16(rb);
    return (uint32_t)__bfloat16_as_ushort(la) | ((uint32_t)__bfloat16_as_ushort(lb) << 16);
}

// ---------------- one-launch weight split prep ----------------
struct PrepSrc { const float* s[8]; };
__constant__ int c_woff[9] = {WOFF_IN, WOFF_GCN, WOFF_ENC, WOFF_MU, WOFF_STD,
                              WOFF_D0, WOFF_D1, WOFF_D2, WTOT};
__global__ void k_prep_all(PrepSrc ps, __nv_bfloat16* __restrict__ hi,
                           __nv_bfloat16* __restrict__ lo)
{
    int i = blockIdx.x * blockDim.x + threadIdx.x;
    if (i >= WTOT) return;
    int r = 0;
#pragma unroll
    for (int k = 1; k < 8; k++) if (i >= c_woff[k]) r = k;
    float v = ps.s[r][i - c_woff[r]];
    __nv_bfloat16 h = __float2bfloat16(v);
    hi[i] = h;
    lo[i] = __float2bfloat16(v - __bfloat162float(h));
}

// ---------------- CSR build ----------------
__global__ void k_zero2(int* a, int* b, int n) {
    int i = blockIdx.x * blockDim.x + threadIdx.x;
    if (i < n) { a[i] = 0; b[i] = 0; }
}
__global__ void k_indeg(const int* __restrict__ dst, int* cnt, int E) {
    int i = blockIdx.x * blockDim.x + threadIdx.x;
    if (i < E) atomicAdd(&cnt[dst[i]], 1);
}
__global__ void k_deg_fin(const int* __restrict__ cnt, float* dinv, int n) {
    int i = blockIdx.x * blockDim.x + threadIdx.x;
    if (i < n) dinv[i] = rsqrtf((float)cnt[i] + 1.f);
}
__global__ void k_scan1(const int* __restrict__ cnt, int* bsum, int* excl, int n) {
    __shared__ int sh[256];
    int t = threadIdx.x, i = blockIdx.x * 256 + t;
    int v = (i < n) ? cnt[i] : 0;
    sh[t] = v;
    __syncthreads();
    for (int o = 1; o < 256; o <<= 1) {
        int x = (t >= o) ? sh[t - o] : 0;
        __syncthreads();
        sh[t] += x;
        __syncthreads();
    }
    if (i < n) excl[i] = sh[t] - v;
    if (t == 255) bsum[blockIdx.x] = sh[255];
}
__global__ void k_scan2(const int* __restrict__ bsum, int* boff, int nb) {
    __shared__ int sh[256];
    int t = threadIdx.x;
    int v = (t < nb) ? bsum[t] : 0;
    sh[t] = v;
    __syncthreads();
    for (int o = 1; o < 256; o <<= 1) {
        int x = (t >= o) ? sh[t - o] : 0;
        __syncthreads();
        sh[t] += x;
        __syncthreads();
    }
    if (t < nb) boff[t] = sh[t] - v;
}
__global__ void k_scan3(const int* __restrict__ excl, const int* __restrict__ boff,
                        int* eoff, int n, int E) {
    int i = blockIdx.x * blockDim.x + threadIdx.x;
    if (i < n) eoff[i] = excl[i] + boff[i >> 8];
    if (i == 0) eoff[n] = E;
}
__global__ void k_fill(const int* __restrict__ src, const int* __restrict__ dst,
                       const float* __restrict__ dinv, const int* __restrict__ eoff,
                       int* cur, int* esrc, float* ew, int E) {
    int i = blockIdx.x * blockDim.x + threadIdx.x;
    if (i >= E) return;
    int d = dst[i], s = src[i];
    int pos = eoff[d] + atomicAdd(&cur[d], 1);
    esrc[pos] = s;
    ew[pos] = dinv[s] * dinv[d];
}

// ---------------- gather-reduce ----------------
__global__ __launch_bounds__(256) void k_gather(
    const float* __restrict__ a, const int* __restrict__ eoff,
    const int* __restrict__ esrc, const float* __restrict__ ew,
    const float* __restrict__ dinv, const float* __restrict__ bias,
    __nv_bfloat16* __restrict__ ohi, __nv_bfloat16* __restrict__ olo, int n)
{
    int node = blockIdx.x * 8 + (threadIdx.x >> 5);
    if (node >= n) return;
    int lane = threadIdx.x & 31;
    int c4 = lane * 4;
    float dv = dinv[node];
    float sc = dv * dv;
    float4 v = *(const float4*)(a + (size_t)node * 128 + c4);
    float a0 = v.x * sc + bias[c4 + 0];
    float a1 = v.y * sc + bias[c4 + 1];
    float a2 = v.z * sc + bias[c4 + 2];
    float a3 = v.w * sc + bias[c4 + 3];
    int e0 = eoff[node], e1 = eoff[node + 1];
#pragma unroll 4
    for (int i = e0; i < e1; i++) {
        int s = esrc[i];
        float w = ew[i];
        float4 u = *(const float4*)(a + (size_t)s * 128 + c4);
        a0 += w * u.x; a1 += w * u.y; a2 += w * u.z; a3 += w * u.w;
    }
    uint2 hv, lv;
    hv.x = pack2bf(a0, a1);    hv.y = pack2bf(a2, a3);
    lv.x = pack2bf_lo(a0, a1); lv.y = pack2bf_lo(a2, a3);
    *(uint2*)(ohi + (size_t)node * 128 + c4) = hv;
    *(uint2*)(olo + (size_t)node * 128 + c4) = lv;
}

// ---------------- WMMA GEMM, W chunked by 64 rows for occ 2 ----------------
template <int KI, int KO, int ACT, bool APL, bool OPL>
__global__ __launch_bounds__(256, 2) void wm2(
    const float* __restrict__ Af,
    const __nv_bfloat16* __restrict__ Ahi, const __nv_bfloat16* __restrict__ Alo, int lda,
    const __nv_bfloat16* __restrict__ Whi, const __nv_bfloat16* __restrict__ Wlo,
    const float* __restrict__ bias,
    float* __restrict__ Cf, __nv_bfloat16* __restrict__ Chi, __nv_bfloat16* __restrict__ Clo,
    int ldc, int n)
{
    constexpr int KC  = (KI < 128) ? KI : 128;
    constexpr int NCH = KI / KC;
    constexpr int WR  = (KC < 64) ? KC : 64;
    constexpr int NW  = KC / WR;
    constexpr int LDA = KC + 8;
    constexpr int LDW = KO + 8;
    constexpr int NJT = KO / 32;
    constexpr int AE  = 128 * LDA;
    constexpr int WE  = WR * LDW;

    extern __shared__ char smraw[];
    __nv_bfloat16* sAhi = (__nv_bfloat16*)smraw;
    __nv_bfloat16* sAlo = sAhi + AE;
    __nv_bfloat16* sWhi = sAlo + AE;
    __nv_bfloat16* sWlo = sWhi + WE;

    const int tid  = threadIdx.x;
    const int wid  = tid >> 5;
    const int lane = tid & 31;
    const int rg   = wid >> 1;
    const int cg   = wid & 1;
    const int row0 = blockIdx.x * 128;

    wmma::fragment<wmma::accumulator, 16, 16, 16, float> acc[2][NJT];
#pragma unroll
    for (int i = 0; i < 2; i++)
#pragma unroll
        for (int j = 0; j < NJT; j++) wmma::fill_fragment(acc[i][j], 0.f);

    const uint32_t sAhiB = smem_u32(sAhi);
    const uint32_t sAloB = smem_u32(sAlo);
    const uint32_t sWhiB = smem_u32(sWhi);
    const uint32_t sWloB = smem_u32(sWlo);

    for (int ch = 0; ch < NCH; ch++) {
        if (ch) __syncthreads();
        // ---- A chunk ----
        if (APL) {
            constexpr int U = KC / 8;
            for (int i = tid; i < 128 * U; i += 256) {
                int r = i / U, u = i % U;
                size_t g = (size_t)(row0 + r) * lda + ch * KC + u * 8;
                uint32_t d = (uint32_t)(r * LDA + u * 8) * 2;
                cpa16(sAhiB + d, Ahi + g);
                cpa16(sAloB + d, Alo + g);
            }
        } else {
            constexpr int Q = KC / 4;
            for (int i = tid; i < 128 * Q; i += 256) {
                int r = i / Q, q = i % Q;
                float4 v = make_float4(0.f, 0.f, 0.f, 0.f);
                if (row0 + r < n)
                    v = *(const float4*)(Af + (size_t)(row0 + r) * lda + ch * KC + 4 * q);
                uint2 hv, lv;
                hv.x = pack2bf(v.x, v.y);    hv.y = pack2bf(v.z, v.w);
                lv.x = pack2bf_lo(v.x, v.y); lv.y = pack2bf_lo(v.z, v.w);
                *(uint2*)(sAhi + r * LDA + 4 * q) = hv;
                *(uint2*)(sAlo + r * LDA + 4 * q) = lv;
            }
        }
        // ---- W chunks ----
        for (int wch = 0; wch < NW; wch++) {
            if (wch) __syncthreads();
            {
                constexpr int U = KO / 8;
                for (int i = tid; i < WR * U; i += 256) {
                    int r = i / U, u = i % U;
                    size_t g = (size_t)(ch * KC + wch * WR + r) * KO + u * 8;
                    uint32_t d = (uint32_t)(r * LDW + u * 8) * 2;
                    cpa16(sWhiB + d, Whi + g);
                    cpa16(sWloB + d, Wlo + g);
                }
            }
            CPA_COMMIT();
            CPA_WAIT();
            __syncthreads();

#pragma unroll
            for (int k = 0; k < WR / 16; k++) {
                const int ks = wch * (WR / 16) + k;
                wmma::fragment<wmma::matrix_a, 16, 16, 16, __nv_bfloat16, wmma::row_major> ah[2], al[2];
#pragma unroll
                for (int i = 0; i < 2; i++) {
                    int r = rg * 32 + i * 16;
                    wmma::load_matrix_sync(ah[i], sAhi + r * LDA + ks * 16, LDA);
                    wmma::load_matrix_sync(al[i], sAlo + r * LDA + ks * 16, LDA);
                }
#pragma unroll
                for (int j = 0; j < NJT; j++) {
                    int c = cg * (KO / 2) + j * 16;
                    wmma::fragment<wmma::matrix_b, 16, 16, 16, __nv_bfloat16, wmma::row_major> bh, bl;
                    wmma::load_matrix_sync(bh, sWhi + k * 16 * LDW + c, LDW);
                    wmma::load_matrix_sync(bl, sWlo + k * 16 * LDW + c, LDW);
#pragma unroll
                    for (int i = 0; i < 2; i++) {
                        wmma::mma_sync(acc[i][j], ah[i], bh, acc[i][j]);
                        wmma::mma_sync(acc[i][j], ah[i], bl, acc[i][j]);
                        wmma::mma_sync(acc[i][j], al[i], bh, acc[i][j]);
                    }
                }
            }
        }
    }
    __syncthreads();

    float* stage = (float*)smraw + wid * 320;
    const int r8 = lane >> 1;
    const int c8 = (lane & 1) * 8;
#pragma unroll
    for (int i = 0; i < 2; i++) {
        const int grow = row0 + rg * 32 + i * 16 + r8;
#pragma unroll
        for (int j = 0; j < NJT; j++) {
            wmma::store_matrix_sync(stage, acc[i][j], 20, wmma::mem_row_major);
            __syncwarp();
            if (grow < n) {
                const int col = cg * (KO / 2) + j * 16 + c8;
                float o[8];
#pragma unroll
                for (int q = 0; q < 8; q++) {
                    float v = stage[r8 * 20 + c8 + q];
                    if (ACT != 4) v += bias[col + q];
                    o[q] = apply_act<ACT>(v);
                }
                if (OPL) {
                    uint4 hv, lv;
                    hv.x = pack2bf(o[0], o[1]); hv.y = pack2bf(o[2], o[3]);
                    hv.z = pack2bf(o[4], o[5]); hv.w = pack2bf(o[6], o[7]);
                    lv.x = pack2bf_lo(o[0], o[1]); lv.y = pack2bf_lo(o[2], o[3]);
                    lv.z = pack2bf_lo(o[4], o[5]); lv.w = pack2bf_lo(o[6], o[7]);
                    *(uint4*)(Chi + (size_t)grow * ldc + col) = hv;
                    *(uint4*)(Clo + (size_t)grow * ldc + col) = lv;
                } else {
                    float* p = Cf + (size_t)grow * ldc + col;
                    *(float4*)(p + 0) = make_float4(o[0], o[1], o[2], o[3]);
                    *(float4*)(p + 4) = make_float4(o[4], o[5], o[6], o[7]);
                }
            }
            __syncwarp();
        }
    }
}

// ---------------- fused encoder block with weight prefetch ----------------
#define EF_LDA 136
#define EF_AE  (128 * EF_LDA)
#define EF_SMEM (4 * EF_AE * 2 + 128 * 132 * 4 + 8 * 320 * 4)

__global__ __launch_bounds__(256) void enc_fused(
    const __nv_bfloat16* __restrict__ Bhi, const __nv_bfloat16* __restrict__ Blo,
    const __nv_bfloat16* __restrict__ whi, const __nv_bfloat16* __restrict__ wlo,
    const float* __restrict__ b_enc, const float* __restrict__ b_mu,
    const float* __restrict__ b_std, const float* __restrict__ eps,
    __nv_bfloat16* __restrict__ hhi, __nv_bfloat16* __restrict__ hlo,
    float* __restrict__ mu_out, float* __restrict__ sd_out, int write_musd, int n)
{
    extern __shared__ char smraw[];
    __nv_bfloat16* sAhi = (__nv_bfloat16*)smraw;
    __nv_bfloat16* sAlo = sAhi + EF_AE;
    __nv_bfloat16* sWhi = sAlo + EF_AE;
    __nv_bfloat16* sWlo = sWhi + EF_AE;
    float* sMu   = (float*)(sWlo + EF_AE);
    float* stageB = sMu + 128 * 132;

    const int tid  = threadIdx.x;
    const int wid  = tid >> 5;
    const int lane = tid & 31;
    const int rg   = wid >> 1;
    const int cg   = wid & 1;
    const int row0 = blockIdx.x * 128;
    const int r8   = lane >> 1;
    const int c8   = (lane & 1) * 8;
    float* stage = stageB + wid * 320;

    const uint32_t sAhiB = smem_u32(sAhi);
    const uint32_t sAloB = smem_u32(sAlo);
    const uint32_t sWhiB = smem_u32(sWhi);
    const uint32_t sWloB = smem_u32(sWlo);

    // ---- preload input planes + layer-0 weights ----
    for (int i = tid; i < 128 * 16; i += 256) {
        int r = i >> 4, u = i & 15;
        size_t g = (size_t)(row0 + r) * 128 + u * 8;
        uint32_t d = (uint32_t)(r * EF_LDA + u * 8) * 2;
        cpa16(sAhiB + d, Bhi + g);
        cpa16(sAloB + d, Blo + g);
    }
    {
        const __nv_bfloat16* Wh = whi + WOFF_ENC;
        const __nv_bfloat16* Wl = wlo + WOFF_ENC;
        for (int i = tid; i < 128 * 16; i += 256) {
            int r = i >> 4, u = i & 15;
            uint32_t d = (uint32_t)(r * EF_LDA + u * 8) * 2;
            cpa16(sWhiB + d, Wh + r * 128 + u * 8);
            cpa16(sWloB + d, Wl + r * 128 + u * 8);
        }
    }
    CPA_COMMIT();
    CPA_WAIT();
    __syncthreads();

    for (int l = 0; l < 7; l++) {
        // ---- MMA ----
        wmma::fragment<wmma::accumulator, 16, 16, 16, float> acc[2][4];
#pragma unroll
        for (int i = 0; i < 2; i++)
#pragma unroll
            for (int j = 0; j < 4; j++) wmma::fill_fragment(acc[i][j], 0.f);
#pragma unroll
        for (int k = 0; k < 8; k++) {
            wmma::fragment<wmma::matrix_a, 16, 16, 16, __nv_bfloat16, wmma::row_major> ah[2], al[2];
#pragma unroll
            for (int i = 0; i < 2; i++) {
                int r = rg * 32 + i * 16;
                wmma::load_matrix_sync(ah[i], sAhi + r * EF_LDA + k * 16, EF_LDA);
                wmma::load_matrix_sync(al[i], sAlo + r * EF_LDA + k * 16, EF_LDA);
            }
#pragma unroll
            for (int j = 0; j < 4; j++) {
                int c = cg * 64 + j * 16;
                wmma::fragment<wmma::matrix_b, 16, 16, 16, __nv_bfloat16, wmma::row_major> bh, bl;
                wmma::load_matrix_sync(bh, sWhi + k * 16 * EF_LDA + c, EF_LDA);
                wmma::load_matrix_sync(bl, sWlo + k * 16 * EF_LDA + c, EF_LDA);
#pragma unroll
                for (int i = 0; i < 2; i++) {
                    wmma::mma_sync(acc[i][j], ah[i], bh, acc[i][j]);
                    wmma::mma_sync(acc[i][j], ah[i], bl, acc[i][j]);
                    wmma::mma_sync(acc[i][j], al[i], bh, acc[i][j]);
                }
            }
        }
        __syncthreads();   // MMA reads of sW/sA complete

        // ---- prefetch next layer's weights (overlaps epilogue) ----
        if (l < 6) {
            int nw = l + 1;
            int woff = (nw < 5) ? (WOFF_ENC + nw * 16384) : ((nw == 5) ? WOFF_MU : WOFF_STD);
            const __nv_bfloat16* Wh = whi + woff;
            const __nv_bfloat16* Wl = wlo + woff;
            for (int i = tid; i < 128 * 16; i += 256) {
                int r = i >> 4, u = i & 15;
                uint32_t d = (uint32_t)(r * EF_LDA + u * 8) * 2;
                cpa16(sWhiB + d, Wh + r * 128 + u * 8);
                cpa16(sWloB + d, Wl + r * 128 + u * 8);
            }
            CPA_COMMIT();
        }

        // ---- epilogue ----
#pragma unroll
        for (int i = 0; i < 2; i++) {
            const int lrow = rg * 32 + i * 16 + r8;
            const int grow = row0 + lrow;
#pragma unroll
            for (int j = 0; j < 4; j++) {
                wmma::store_matrix_sync(stage, acc[i][j], 20, wmma::mem_row_major);
                __syncwarp();
                const int col = cg * 64 + j * 16 + c8;
                if (l < 5) {
                    float o[8];
#pragma unroll
                    for (int q = 0; q < 8; q++) {
                        float v = stage[r8 * 20 + c8 + q] + b_enc[l * 128 + col + q];
                        o[q] = 1.f / (1.f + expf(-v));
                    }
                    uint4 hv, lv;
                    hv.x = pack2bf(o[0], o[1]); hv.y = pack2bf(o[2], o[3]);
                    hv.z = pack2bf(o[4], o[5]); hv.w = pack2bf(o[6], o[7]);
                    lv.x = pack2bf_lo(o[0], o[1]); lv.y = pack2bf_lo(o[2], o[3]);
                    lv.z = pack2bf_lo(o[4], o[5]); lv.w = pack2bf_lo(o[6], o[7]);
                    *(uint4*)(sAhi + lrow * EF_LDA + col) = hv;
                    *(uint4*)(sAlo + lrow * EF_LDA + col) = lv;
                } else if (l == 5) {
                    float o[8];
#pragma unroll
                    for (int q = 0; q < 8; q++) {
                        o[q] = stage[r8 * 20 + c8 + q] + b_mu[col + q];
                        sMu[lrow * 132 + col + q] = o[q];
                    }
                    if (write_musd && grow < n) {
                        float* p = mu_out + (size_t)grow * 128 + col;
                        *(float4*)(p + 0) = make_float4(o[0], o[1], o[2], o[3]);
                        *(float4*)(p + 4) = make_float4(o[4], o[5], o[6], o[7]);
                    }
                } else {
                    float s[8], h[8];
                    float4 e0 = make_float4(0.f, 0.f, 0.f, 0.f), e1 = e0;
                    if (grow < n) {
                        e0 = *(const float4*)(eps + (size_t)grow * 128 + col);
                        e1 = *(const float4*)(eps + (size_t)grow * 128 + col + 4);
                    }
                    float ev[8] = {e0.x, e0.y, e0.z, e0.w, e1.x, e1.y, e1.z, e1.w};
#pragma unroll
                    for (int q = 0; q < 8; q++) {
                        float z = stage[r8 * 20 + c8 + q] + b_std[col + q] - 5.f;
                        s[q] = fmaxf(z, 0.f) + log1pf(expf(-fabsf(z)));
                        h[q] = sMu[lrow * 132 + col + q] + s[q] * ev[q];
                    }
                    if (grow < n) {
                        uint4 hv, lv;
                        hv.x = pack2bf(h[0], h[1]); hv.y = pack2bf(h[2], h[3]);
                        hv.z = pack2bf(h[4], h[5]); hv.w = pack2bf(h[6], h[7]);
                        lv.x = pack2bf_lo(h[0], h[1]); lv.y = pack2bf_lo(h[2], h[3]);
                        lv.z = pack2bf_lo(h[4], h[5]); lv.w = pack2bf_lo(h[6], h[7]);
                        *(uint4*)(hhi + (size_t)grow * 128 + col) = hv;
                        *(uint4*)(hlo + (size_t)grow * 128 + col) = lv;
                        if (write_musd) {
                            float* p = sd_out + (size_t)grow * 128 + col;
                            *(float4*)(p + 0) = make_float4(s[0], s[1], s[2], s[3]);
                            *(float4*)(p + 4) = make_float4(s[4], s[5], s[6], s[7]);
                        }
                    }
                }
                __syncwarp();
            }
        }
        if (l < 6) {
            CPA_WAIT();
            __syncthreads();   // next weights ready + sA writes visible
        }
    }
}

// ---------------- fused decoder tail: 64->32->16->10 + pool accumulate ----------------
#define TAIL_SMEM (256 * 65 * 4 + (2048 + 512 + 160 + 32 + 16 + 10) * 4)
__global__ __launch_bounds__(256) void k_tail(
    const float* __restrict__ A,
    const float* __restrict__ W3, const float* __restrict__ b3,
    const float* __restrict__ W4, const float* __restrict__ b4,
    const float* __restrict__ Wo, const float* __restrict__ bo,
    const int* __restrict__ bids, float* __restrict__ sums, float* __restrict__ cnt, int n)
{
    extern __shared__ float sm[];
    float* srow = sm;
    float* w3 = srow + 256 * 65;
    float* w4 = w3 + 2048;
    float* wo = w4 + 512;
    float* bb3 = wo + 160;
    float* bb4 = bb3 + 32;
    float* bbo = bb4 + 16;

    const int tid = threadIdx.x;
    const int row0 = blockIdx.x * 256;
    for (int i = tid; i < 2048; i += 256) w3[i] = W3[i];
    for (int i = tid; i < 512; i += 256) w4[i] = W4[i];
    if (tid < 160) wo[tid] = Wo[tid];
    if (tid < 32) bb3[tid] = b3[tid];
    if (tid < 16) bb4[tid] = b4[tid];
    if (tid < 10) bbo[tid] = bo[tid];
    for (int i = tid; i < 256 * 64; i += 256) {
        int r = i >> 6, c = i & 63;
        float v = (row0 + r < n) ? A[(size_t)(row0 + r) * 64 + c] : 0.f;
        srow[r * 65 + c] = v;
    }
    __syncthreads();

    const int row = row0 + tid;
    if (row >= n) return;
    float d0[64];
#pragma unroll
    for (int k = 0; k < 64; k++) d0[k] = srow[tid * 65 + k];
    float d1[32];
#pragma unroll
    for (int j = 0; j < 32; j++) {
        float s = bb3[j];
#pragma unroll
        for (int k = 0; k < 64; k++) s += d0[k] * w3[k * 32 + j];
        d1[j] = fmaxf(s, 0.f);
    }
    float d2[16];
#pragma unroll
    for (int j = 0; j < 16; j++) {
        float s = bb4[j];
#pragma unroll
        for (int k = 0; k < 32; k++) s += d1[k] * w4[k * 16 + j];
        d2[j] = fmaxf(s, 0.f);
    }
    const int b = bids[row];
#pragma unroll
    for (int c = 0; c < 10; c++) {
        float s = bbo[c];
#pragma unroll
        for (int k = 0; k < 16; k++) s += d2[k] * wo[k * 10 + c];
        atomicAdd(&sums[b * 10 + c], 1.f / (1.f + expf(-s)));
    }
    atomicAdd(&cnt[b], 1.f);
}

// ---------------- pooling ----------------
__global__ void k_pool_init(float* sums, float* cnt, int gsz) {
    int i = blockIdx.x * blockDim.x + threadIdx.x;
    if (i < gsz * 10) sums[i] = 0.f;
    if (i < gsz) cnt[i] = 0.f;
}
__global__ void k_pool_fin(const float* __restrict__ sums, const float* __restrict__ cnt,
                           const float* __restrict__ y, float* __restrict__ out,
                           float* __restrict__ yout, int tot)
{
    int i = blockIdx.x * blockDim.x + threadIdx.x;
    if (i >= tot) return;
    out[i] = sums[i] / fmaxf(cnt[i / 10], 1.f);
    yout[i] = y[i];
}

// ---------------- host helpers ----------------
template <int KI, int KO, int ACT, bool APL, bool OPL>
static void run2(const float* Af, const __nv_bfloat16* Ahi, const __nv_bfloat16* Alo, int lda,
                 const __nv_bfloat16* Whi, const __nv_bfloat16* Wlo, const float* bias,
                 float* Cf, __nv_bfloat16* Chi, __nv_bfloat16* Clo, int ldc, int n)
{
    constexpr int KC = (KI < 128) ? KI : 128;
    constexpr int WR = (KC < 64) ? KC : 64;
    constexpr int SMB = (128 * (KC + 8) + WR * (KO + 8)) * 2 * 2;
    cudaFuncSetAttribute(wm2<KI, KO, ACT, APL, OPL>,
                         cudaFuncAttributeMaxDynamicSharedMemorySize, SMB);
    wm2<KI, KO, ACT, APL, OPL><<<(n + 127) / 128, 256, SMB>>>(
        Af, Ahi, Alo, lda, Whi, Wlo, bias, Cf, Chi, Clo, ldc, n);
}

extern "C" void kernel_launch(void* const* d_in, const int* in_sizes, int n_in,
                              void* d_out, int out_size)
{
    const float* x     = (const float*)d_in[0];
    const int*   ei    = (const int*)d_in[1];
    const int*   bids  = (const int*)d_in[2];
    const float* y     = (const float*)d_in[3];
    const float* eps   = (const float*)d_in[4];
    const float* W_in  = (const float*)d_in[5];
    const float* b_in  = (const float*)d_in[6];
    const float* W_gcn = (const float*)d_in[7];
    const float* b_gcn = (const float*)d_in[8];
    const float* W_enc = (const float*)d_in[9];
    const float* b_enc = (const float*)d_in[10];
    const float* W_mu  = (const float*)d_in[11];
    const float* b_mu  = (const float*)d_in[12];
    const float* W_std = (const float*)d_in[13];
    const float* b_std = (const float*)d_in[14];
    const float* Wd0 = (const float*)d_in[15]; const float* bd0 = (const float*)d_in[16];
    const float* Wd1 = (const float*)d_in[17]; const float* bd1 = (const float*)d_in[18];
    const float* Wd2 = (const float*)d_in[19]; const float* bd2 = (const float*)d_in[20];
    const float* Wd3 = (const float*)d_in[21]; const float* bd3 = (const float*)d_in[22];
    const float* Wd4 = (const float*)d_in[23]; const float* bd4 = (const float*)d_in[24];
    const float* Wo  = (const float*)d_in[25]; const float* bo  = (const float*)d_in[26];

    const int N = in_sizes[2];
    const int E = in_sizes[1] / 2;
    const int G = in_sizes[3] / 10;
    const int* src = ei;
    const int* dst = ei + E;

    float *dinv, *a, *b, *sums, *cntf, *ew;
    int *cnti, *cur, *excl, *bsum, *boff, *eoff, *esrc;
    __nv_bfloat16 *hhi, *hlo, *p0hi, *p0lo, *p1hi, *p1lo, *whi, *wlo;
    cudaGetSymbolAddress((void**)&dinv, g_dinv);
    cudaGetSymbolAddress((void**)&a,    g_a);
    cudaGetSymbolAddress((void**)&b,    g_b);
    cudaGetSymbolAddress((void**)&sums, g_sums);
    cudaGetSymbolAddress((void**)&cntf, g_cntf);
    cudaGetSymbolAddress((void**)&cnti, g_cnti);
    cudaGetSymbolAddress((void**)&cur,  g_cur);
    cudaGetSymbolAddress((void**)&excl, g_excl);
    cudaGetSymbolAddress((void**)&bsum, g_bsum);
    cudaGetSymbolAddress((void**)&boff, g_boff);
    cudaGetSymbolAddress((void**)&eoff, g_eoff);
    cudaGetSymbolAddress((void**)&esrc, g_esrc);
    cudaGetSymbolAddress((void**)&ew,   g_ew);
    cudaGetSymbolAddress((void**)&hhi,  g_hhi);
    cudaGetSymbolAddress((void**)&hlo,  g_hlo);
    cudaGetSymbolAddress((void**)&p0hi, g_p0hi);
    cudaGetSymbolAddress((void**)&p0lo, g_p0lo);
    cudaGetSymbolAddress((void**)&p1hi, g_p1hi);
    cudaGetSymbolAddress((void**)&p1lo, g_p1lo);
    cudaGetSymbolAddress((void**)&whi,  g_whi);
    cudaGetSymbolAddress((void**)&wlo,  g_wlo);

    float* out    = (float*)d_out;
    float* mu_out = out + (size_t)G * 10;
    float* sd_out = mu_out + (size_t)N * 128;
    float* y_out  = sd_out + (size_t)N * 128;

    const int TB = 256;
    const int gb128 = (N + 127) / 128;
    const int nb = (N + 255) / 256;

    // ---- weight split prep ----
    {
        PrepSrc ps;
        ps.s[0] = W_in;  ps.s[1] = W_gcn; ps.s[2] = W_enc; ps.s[3] = W_mu;
        ps.s[4] = W_std; ps.s[5] = Wd0;   ps.s[6] = Wd1;   ps.s[7] = Wd2;
        k_prep_all<<<(WTOT + 255) / 256, 256>>>(ps, whi, wlo);
    }

    // ---- CSR build + degrees ----
    k_zero2<<<nb, TB>>>(cnti, cur, N);
    k_indeg<<<(E + TB - 1) / TB, TB>>>(dst, cnti, E);
    k_deg_fin<<<nb, TB>>>(cnti, dinv, N);
    k_scan1<<<nb, 256>>>(cnti, bsum, excl, N);
    k_scan2<<<1, 256>>>(bsum, boff, nb);
    k_scan3<<<nb, 256>>>(excl, boff, eoff, N, E);
    k_fill<<<(E + TB - 1) / TB, TB>>>(src, dst, dinv, eoff, cur, esrc, ew, E);
    k_pool_init<<<(G * 10 + TB - 1) / TB, TB>>>(sums, cntf, G);

    // ---- input layer ----
    run2<32, 128, 1, false, true>(x, nullptr, nullptr, 32,
                                  whi + WOFF_IN, wlo + WOFF_IN, b_in,
                                  nullptr, hhi, hlo, 128, N);

    cudaFuncSetAttribute(enc_fused, cudaFuncAttributeMaxDynamicSharedMemorySize, EF_SMEM);
    cudaFuncSetAttribute(k_tail, cudaFuncAttributeMaxDynamicSharedMemorySize, TAIL_SMEM);

    for (int hop = 0; hop < 3; hop++) {
        run2<128, 128, 4, true, false>(nullptr, hhi, hlo, 128,
                                       whi + WOFF_GCN, wlo + WOFF_GCN, nullptr,
                                       a, nullptr, nullptr, 128, N);
        k_gather<<<(N + 7) / 8, 256>>>(a, eoff, esrc, ew, dinv, b_gcn, p0hi, p0lo, N);
        enc_fused<<<gb128, 256, EF_SMEM>>>(p0hi, p0lo, whi, wlo, b_enc, b_mu, b_std,
                                           eps + (size_t)hop * N * 128,
                                           hhi, hlo, mu_out, sd_out,
                                           (hop == 2) ? 1 : 0, N);
    }

    // ---- decoder ----
    run2<128, 128, 2, true, true>(nullptr, hhi, hlo, 128,
                                  whi + WOFF_D0, wlo + WOFF_D0, bd0,
                                  nullptr, p1hi, p1lo, 256, N);
    run2<128, 128, 2, true, true>(nullptr, hhi, hlo, 128,
                                  whi + WOFF_D0 + 128, wlo + WOFF_D0 + 128, bd0 + 128,
                                  nullptr, p1hi + 128, p1lo + 128, 256, N);
    run2<256, 128, 2, true, true>(nullptr, p1hi, p1lo, 256,
                                  whi + WOFF_D1, wlo + WOFF_D1, bd1,
                                  nullptr, p0hi, p0lo, 128, N);
    run2<128, 64, 2, true, false>(nullptr, p0hi, p0lo, 128,
                                  whi + WOFF_D2, wlo + WOFF_D2, bd2,
                                  b, nullptr, nullptr, 64, N);
    k_tail<<<(N + 255) / 256, 256, TAIL_SMEM>>>(b, Wd3, bd3, Wd4, bd4, Wo, bo,
                                                bids, sums, cntf, N);
    k_pool_fin<<<(G * 10 + TB - 1) / TB, TB>>>(sums, cntf, y, out, y_out, G * 10);
}